// round 1
// baseline (speedup 1.0000x reference)
#include <cuda_runtime.h>
#include <math.h>

#define NMESH 10242
#define NGRID 65160
#define NEDGES 195480
#define DD 512
#define OUTD 471

// Scratch (allocation-free rule: __device__ globals)
__device__ float g_e[(size_t)NEDGES * DD];     // edge embedding (residual source)
__device__ float g_h[(size_t)NEDGES * DD];     // hidden buffer (emb hidden, then edge hidden)
__device__ float g_agg[(size_t)NGRID * DD];    // segment sum
__device__ float g_nh[(size_t)NGRID * DD];     // node hidden
__device__ float g_grid2[(size_t)NGRID * DD];  // grid residual output
__device__ float g_oh[(size_t)NGRID * DD];     // out hidden

__device__ __forceinline__ float silu_f(float v) {
    return v / (1.0f + __expf(-v));
}

// ---------------------------------------------------------------------------
// Edge embedding layer 1: K=4, trivial per-element kernel.
// h[i,j] = silu(sum_k attrs[i,k] * w0[k,j] + b0[j])
// ---------------------------------------------------------------------------
__global__ void k_emb_l1(const float* __restrict__ attrs,
                         const float* __restrict__ w0,
                         const float* __restrict__ b0) {
    long long idx = (long long)blockIdx.x * blockDim.x + threadIdx.x;
    if (idx >= (long long)NEDGES * DD) return;
    int i = (int)(idx / DD);
    int j = (int)(idx % DD);
    float a0 = attrs[i * 4 + 0], a1 = attrs[i * 4 + 1];
    float a2 = attrs[i * 4 + 2], a3 = attrs[i * 4 + 3];
    float v = b0[j];
    v += a0 * w0[0 * DD + j];
    v += a1 * w0[1 * DD + j];
    v += a2 * w0[2 * DD + j];
    v += a3 * w0[3 * DD + j];
    g_h[idx] = silu_f(v);
}

__global__ void k_zero(float* __restrict__ p, long long n) {
    long long i = (long long)blockIdx.x * blockDim.x + threadIdx.x;
    long long stride = (long long)gridDim.x * blockDim.x;
    for (; i < n; i += stride) p[i] = 0.0f;
}

// ---------------------------------------------------------------------------
// Generic tiled GEMM: C[M,N] = epilogue(A @ W + bias)
// AMODE 0: A = A0[M,K]
// AMODE 1: A row m = concat( A0[gidx0[m], 0:512], A1[gidx1[m], 0:512], A2[m, 0:512] ), K=1536
// AMODE 2: A row m = concat( A0[m, 0:512], A1[m, 0:512] ), K=1024
// Epilogue flags: SILU, RESID (+= resid[m,n]), STORE (write C), SCATTER
// (atomicAdd into scat[scat_idx[m]*N + n]).
// Tile: 64x64, BK=16, 256 threads, 4x4 per thread.
// ---------------------------------------------------------------------------
template <int AMODE, bool SILU, bool RESID, bool SCATTER, bool STORE>
__global__ void __launch_bounds__(256)
k_gemm(const float* __restrict__ A0, const float* __restrict__ A1,
       const float* __restrict__ A2,
       const int* __restrict__ gidx0, const int* __restrict__ gidx1,
       const float* __restrict__ W, const float* __restrict__ bias,
       const float* __restrict__ resid,
       float* __restrict__ C,
       float* __restrict__ scat, const int* __restrict__ scat_idx,
       int M, int N, int K) {
    __shared__ float As[16][68];
    __shared__ float Ws[16][68];
    __shared__ int sI0[64];
    __shared__ int sI1[64];

    const int m0 = blockIdx.y * 64;
    const int n0 = blockIdx.x * 64;
    const int tid = threadIdx.x;

    if (AMODE == 1) {
        if (tid < 64) {
            int r = m0 + tid;
            sI0[tid] = (r < M) ? gidx0[r] : 0;
            sI1[tid] = (r < M) ? gidx1[r] : 0;
        }
        __syncthreads();
    }

    const int a_row = tid >> 2;          // 0..63
    const int a_k4  = (tid & 3) * 4;     // 0,4,8,12
    const int w_k   = tid >> 4;          // 0..15
    const int w_n   = (tid & 15) * 4;    // 0..60
    const int ty    = tid >> 4;          // 0..15
    const int tx    = tid & 15;          // 0..15

    const int gRow = m0 + a_row;
    float acc[4][4] = {};

    for (int k0 = 0; k0 < K; k0 += 16) {
        // ---- load A tile (64 rows x 16 k), stored transposed As[k][row]
#pragma unroll
        for (int c = 0; c < 4; c++) {
            int k = k0 + a_k4 + c;
            float v = 0.0f;
            if (gRow < M && k < K) {
                if (AMODE == 0) {
                    v = A0[(size_t)gRow * K + k];
                } else if (AMODE == 1) {
                    if (k < DD)           v = A0[(size_t)sI0[a_row] * DD + k];
                    else if (k < 2 * DD)  v = A1[(size_t)sI1[a_row] * DD + (k - DD)];
                    else                  v = A2[(size_t)gRow * DD + (k - 2 * DD)];
                } else {  // AMODE 2
                    if (k < DD) v = A0[(size_t)gRow * DD + k];
                    else        v = A1[(size_t)gRow * DD + (k - DD)];
                }
            }
            As[a_k4 + c][a_row] = v;
        }
        // ---- load W tile (16 k x 64 n)
#pragma unroll
        for (int c = 0; c < 4; c++) {
            int n = n0 + w_n + c;
            int k = k0 + w_k;
            Ws[w_k][w_n + c] = (k < K && n < N) ? W[(size_t)k * N + n] : 0.0f;
        }
        __syncthreads();

#pragma unroll
        for (int kk = 0; kk < 16; kk++) {
            float a[4], b[4];
#pragma unroll
            for (int i = 0; i < 4; i++) a[i] = As[kk][ty * 4 + i];
#pragma unroll
            for (int j = 0; j < 4; j++) b[j] = Ws[kk][tx * 4 + j];
#pragma unroll
            for (int i = 0; i < 4; i++)
#pragma unroll
                for (int j = 0; j < 4; j++)
                    acc[i][j] += a[i] * b[j];
        }
        __syncthreads();
    }

    // ---- epilogue
#pragma unroll
    for (int i = 0; i < 4; i++) {
        int m = m0 + ty * 4 + i;
        if (m >= M) continue;
        int sIdx = 0;
        if (SCATTER) sIdx = scat_idx[m];
#pragma unroll
        for (int j = 0; j < 4; j++) {
            int n = n0 + tx * 4 + j;
            if (n >= N) continue;
            float v = acc[i][j] + bias[n];
            if (SILU) v = silu_f(v);
            if (RESID) v += resid[(size_t)m * N + n];
            if (STORE) C[(size_t)m * N + n] = v;
            if (SCATTER) atomicAdd(&scat[(size_t)sIdx * N + n], v);
        }
    }
}

extern "C" void kernel_launch(void* const* d_in, const int* in_sizes, int n_in,
                              void* d_out, int out_size) {
    const float* mesh    = (const float*)d_in[0];
    const float* grid    = (const float*)d_in[1];
    const float* attrs   = (const float*)d_in[2];
    const int*   esrc    = (const int*)d_in[3];
    const int*   edst    = (const int*)d_in[4];
    const float* emb_w0  = (const float*)d_in[5];
    const float* emb_b0  = (const float*)d_in[6];
    const float* emb_w1  = (const float*)d_in[7];
    const float* emb_b1  = (const float*)d_in[8];
    const float* edge_w0 = (const float*)d_in[9];
    const float* edge_b0 = (const float*)d_in[10];
    const float* edge_w1 = (const float*)d_in[11];
    const float* edge_b1 = (const float*)d_in[12];
    const float* node_w0 = (const float*)d_in[13];
    const float* node_b0 = (const float*)d_in[14];
    const float* node_w1 = (const float*)d_in[15];
    const float* node_b1 = (const float*)d_in[16];
    const float* out_w0  = (const float*)d_in[17];
    const float* out_b0  = (const float*)d_in[18];
    const float* out_w1  = (const float*)d_in[19];
    const float* out_b1  = (const float*)d_in[20];
    float* out = (float*)d_out;

    float *ge, *gh, *gagg, *gnh, *ggrid2, *goh;
    cudaGetSymbolAddress((void**)&ge, g_e);
    cudaGetSymbolAddress((void**)&gh, g_h);
    cudaGetSymbolAddress((void**)&gagg, g_agg);
    cudaGetSymbolAddress((void**)&gnh, g_nh);
    cudaGetSymbolAddress((void**)&ggrid2, g_grid2);
    cudaGetSymbolAddress((void**)&goh, g_oh);

    const int TE = (NEDGES + 63) / 64;   // 3055 edge row-tiles
    const int TG = (NGRID + 63) / 64;    // 1019 grid row-tiles
    const int TN = DD / 64;              // 8 col-tiles for N=512
    const int TO = (OUTD + 63) / 64;     // 8 col-tiles for N=471

    // 1) emb layer 1: g_h = silu(attrs @ emb_w0 + b0)
    {
        long long n = (long long)NEDGES * DD;
        k_emb_l1<<<(unsigned)((n + 255) / 256), 256>>>(attrs, emb_w0, emb_b0);
    }
    // 2) emb layer 2: g_e = g_h @ emb_w1 + b1
    k_gemm<0, false, false, false, true><<<dim3(TN, TE), 256>>>(
        gh, nullptr, nullptr, nullptr, nullptr, emb_w1, emb_b1,
        nullptr, ge, nullptr, nullptr, NEDGES, DD, DD);
    // 3) zero agg
    k_zero<<<1024, 256>>>(gagg, (long long)NGRID * DD);
    // 4) edge layer 1 (fused gather-concat):
    //    g_h = silu( [mesh[src] | grid[dst] | g_e] @ edge_w0 + b0 )
    k_gemm<1, true, false, false, true><<<dim3(TN, TE), 256>>>(
        mesh, grid, ge, esrc, edst, edge_w0, edge_b0,
        nullptr, gh, nullptr, nullptr, NEDGES, DD, 3 * DD);
    // 5) edge layer 2 + residual + fused segment-sum scatter (no store of e_new):
    //    agg[dst[m]] += g_e[m] + g_h @ edge_w1 + b1
    k_gemm<0, false, true, true, false><<<dim3(TN, TE), 256>>>(
        gh, nullptr, nullptr, nullptr, nullptr, edge_w1, edge_b1,
        ge, nullptr, gagg, edst, NEDGES, DD, DD);
    // 6) node layer 1: g_nh = silu( [grid | agg] @ node_w0 + b0 )
    k_gemm<2, true, false, false, true><<<dim3(TN, TG), 256>>>(
        grid, gagg, nullptr, nullptr, nullptr, node_w0, node_b0,
        nullptr, gnh, nullptr, nullptr, NGRID, DD, 2 * DD);
    // 7) node layer 2: g_grid2 = grid + g_nh @ node_w1 + b1
    k_gemm<0, false, true, false, true><<<dim3(TN, TG), 256>>>(
        gnh, nullptr, nullptr, nullptr, nullptr, node_w1, node_b1,
        grid, ggrid2, nullptr, nullptr, NGRID, DD, DD);
    // 8) out layer 1: g_oh = silu(g_grid2 @ out_w0 + b0)
    k_gemm<0, true, false, false, true><<<dim3(TN, TG), 256>>>(
        ggrid2, nullptr, nullptr, nullptr, nullptr, out_w0, out_b0,
        nullptr, goh, nullptr, nullptr, NGRID, DD, DD);
    // 9) out layer 2: out = g_oh @ out_w1 + b1   (N = 471)
    k_gemm<0, false, false, false, true><<<dim3(TO, TG), 256>>>(
        goh, nullptr, nullptr, nullptr, nullptr, out_w1, out_b1,
        nullptr, out, nullptr, nullptr, NGRID, OUTD, DD);
}

// round 6
// speedup vs baseline: 3.5007x; 3.5007x over previous
#include <cuda_runtime.h>
#include <cstdint>

#define NMESH 10242
#define NGRID 65160
#define NEDGES 195480
#define DD 512
#define OUTD 471

#define THREADS 256
#define MT 128          // CTA M tile
#define NT 128          // CTA N tile
#define KCH 32          // K chunk
#define LDS_STRIDE 36   // padded smem row stride (floats)

// ---- smem layout in floats ----
#define SA_OFF 0            // 2 * 128*36 = 9216
#define SB_OFF 9216         // 2 * 128*36
#define SBIAS_OFF 18432     // 128
#define SI0_OFF 18560       // 128 ints
#define SI1_OFF 18688       // 128 ints
#define SIDX_OFF 18816      // 128 ints
#define SMEM_FLOATS 18944
#define SMEM_BYTES (SMEM_FLOATS * 4)

// ---- scratch ----
__device__ float g_e[(size_t)NEDGES * DD];
__device__ float g_h[(size_t)NEDGES * DD];
__device__ float g_agg[(size_t)NGRID * DD];
__device__ float g_nh[(size_t)NGRID * DD];
__device__ float g_grid2[(size_t)NGRID * DD];
__device__ float g_oh[(size_t)NGRID * DD];
__device__ float g_wt[2600448];

#define WT_EMB1   0
#define WT_EDGE0  262144
#define WT_EDGE1  1048576
#define WT_NODE0  1310720
#define WT_NODE1  1835008
#define WT_OUT0   2097152
#define WT_OUT1   2359296

__device__ __forceinline__ uint32_t f2tf32(float f) {
    uint32_t r;
    asm("cvt.rna.tf32.f32 %0, %1;" : "=r"(r) : "f"(f));
    return r;
}
__device__ __forceinline__ float silu_f(float v) { return v / (1.0f + __expf(-v)); }

__device__ __forceinline__ void mma_tf32(float (&d)[4], const uint32_t (&a)[4],
                                         const uint32_t (&b)[2]) {
    asm volatile(
        "mma.sync.aligned.m16n8k8.row.col.f32.tf32.tf32.f32 "
        "{%0,%1,%2,%3}, {%4,%5,%6,%7}, {%8,%9}, {%0,%1,%2,%3};"
        : "+f"(d[0]), "+f"(d[1]), "+f"(d[2]), "+f"(d[3])
        : "r"(a[0]), "r"(a[1]), "r"(a[2]), "r"(a[3]), "r"(b[0]), "r"(b[1]));
}

// ======================= small kernels =======================
__global__ void k_emb_l1(const float* __restrict__ attrs,
                         const float* __restrict__ w0,
                         const float* __restrict__ b0) {
    long long idx = (long long)blockIdx.x * blockDim.x + threadIdx.x;
    if (idx >= (long long)NEDGES * DD) return;
    int i = (int)(idx / DD);
    int j = (int)(idx % DD);
    float v = b0[j];
    v += attrs[i * 4 + 0] * w0[0 * DD + j];
    v += attrs[i * 4 + 1] * w0[1 * DD + j];
    v += attrs[i * 4 + 2] * w0[2 * DD + j];
    v += attrs[i * 4 + 3] * w0[3 * DD + j];
    g_h[idx] = silu_f(v);
}

__global__ void k_zero(float* __restrict__ p, long long n) {
    long long i = (long long)blockIdx.x * blockDim.x + threadIdx.x;
    long long stride = (long long)gridDim.x * blockDim.x;
    for (; i < n; i += stride) p[i] = 0.0f;
}

// Wt[n][k] = rna_tf32(W[k][n])
__global__ void k_transpose(const float* __restrict__ in, float* __restrict__ out,
                            int K, int N) {
    __shared__ float t[32][33];
    int k0 = blockIdx.x * 32, n0 = blockIdx.y * 32;
#pragma unroll
    for (int i = 0; i < 4; i++) {
        int k = k0 + threadIdx.y + i * 8;
        int n = n0 + threadIdx.x;
        t[threadIdx.y + i * 8][threadIdx.x] = (k < K && n < N) ? in[(size_t)k * N + n] : 0.f;
    }
    __syncthreads();
#pragma unroll
    for (int i = 0; i < 4; i++) {
        int n = n0 + threadIdx.y + i * 8;
        int k = k0 + threadIdx.x;
        if (n < N && k < K)
            out[(size_t)n * K + k] = __uint_as_float(f2tf32(t[threadIdx.x][threadIdx.y + i * 8]));
    }
}

// ======================= tf32 mma.sync GEMM =======================
// C[M,N] = epi(A @ W + bias). AMODE 0: plain A0[M,K]; 1: gather-concat
// [A0[gidx0]|A1[gidx1]|A2], K=1536; 2: concat [A0|A1], K=1024.
// Wt pre-transposed [N][K], tf32-rounded. CTA: 128x128, warps 2x4 (64x32 each).
template <int AMODE, bool SILU_, bool RESID_, bool SCATTER_, bool STORE_>
__global__ void __launch_bounds__(THREADS)
k_mma(const float* __restrict__ A0, const float* __restrict__ A1,
      const float* __restrict__ A2,
      const int* __restrict__ gidx0, const int* __restrict__ gidx1,
      const float* __restrict__ Wt, const float* __restrict__ bias,
      const float* __restrict__ resid,
      float* __restrict__ C,
      float* __restrict__ scat, const int* __restrict__ scat_idx,
      int M, int N, int K) {
    extern __shared__ float sm[];
    float* sA = sm + SA_OFF;
    float* sB = sm + SB_OFF;
    float* sbias = sm + SBIAS_OFF;
    int* sI0 = (int*)(sm + SI0_OFF);
    int* sI1 = (int*)(sm + SI1_OFF);
    int* sIdx = (int*)(sm + SIDX_OFF);

    const int tid = threadIdx.x;
    const int lane = tid & 31;
    const int wid = tid >> 5;
    const int m0 = blockIdx.x * MT;
    const int n0 = blockIdx.y * NT;

    if (tid < 128) {
        sbias[tid] = (n0 + tid < N) ? bias[n0 + tid] : 0.0f;
        int gr = m0 + tid; if (gr >= M) gr = M - 1;
        if (AMODE == 1) { sI0[tid] = gidx0[gr]; sI1[tid] = gidx1[gr]; }
        if (SCATTER_) sIdx[tid] = scat_idx[gr];
    }
    __syncthreads();

    const int ldrow = tid >> 3;       // 0..31 (x4 iters -> rows 0..127 via +32)
    const int ldq = tid & 7;          // 16B unit within 32-float row

    float4 ra[4], rb[4];

    auto loadA = [&](int kc0) {
#pragma unroll
        for (int j = 0; j < 4; j++) {
            int row = ldrow + j * 32;
            int gr = m0 + row; if (gr >= M) gr = M - 1;
            const float* src;
            if (AMODE == 0) {
                src = A0 + (size_t)gr * K + kc0;
            } else if (AMODE == 1) {
                if (kc0 < DD)          src = A0 + (size_t)sI0[row] * DD + kc0;
                else if (kc0 < 2 * DD) src = A1 + (size_t)sI1[row] * DD + (kc0 - DD);
                else                   src = A2 + (size_t)gr * DD + (kc0 - 2 * DD);
            } else {
                if (kc0 < DD) src = A0 + (size_t)gr * DD + kc0;
                else          src = A1 + (size_t)gr * DD + (kc0 - DD);
            }
            ra[j] = *(const float4*)(src + ldq * 4);
        }
    };
    auto loadB = [&](int kc0) {
#pragma unroll
        for (int j = 0; j < 4; j++) {
            int row = ldrow + j * 32;
            int n = n0 + row;
            if (n < N) rb[j] = *(const float4*)(Wt + (size_t)n * K + kc0 + ldq * 4);
            else       rb[j] = make_float4(0.f, 0.f, 0.f, 0.f);
        }
    };
    auto stsAB = [&](int buf) {
        float* dA = sA + buf * (128 * LDS_STRIDE);
        float* dB = sB + buf * (128 * LDS_STRIDE);
#pragma unroll
        for (int j = 0; j < 4; j++) {
            int row = ldrow + j * 32;
            float4 v = ra[j];
            uint4 o;
            o.x = f2tf32(v.x); o.y = f2tf32(v.y); o.z = f2tf32(v.z); o.w = f2tf32(v.w);
            *(uint4*)(dA + row * LDS_STRIDE + ldq * 4) = o;
            *(float4*)(dB + row * LDS_STRIDE + ldq * 4) = rb[j];  // pre-rounded
        }
    };

    float acc[4][4][4] = {};
    const int wm = wid >> 2;          // 0..1
    const int wn = wid & 3;           // 0..3
    const int r = lane >> 2;          // 0..7
    const int c = lane & 3;           // 0..3

    const int nch = K / KCH;
    loadA(0); loadB(0);
    stsAB(0);
    __syncthreads();

    for (int ch = 0; ch < nch; ch++) {
        const int buf = ch & 1;
        if (ch + 1 < nch) { loadA((ch + 1) * KCH); loadB((ch + 1) * KCH); }

        const float* bA = sA + buf * (128 * LDS_STRIDE) + (wm * 64 + r) * LDS_STRIDE + c;
        const float* bB = sB + buf * (128 * LDS_STRIDE) + (wn * 32 + r) * LDS_STRIDE + c;
#pragma unroll
        for (int kk = 0; kk < 4; kk++) {
            const int kb = kk * 8;
            uint32_t af[4][4], bf[4][2];
#pragma unroll
            for (int mf = 0; mf < 4; mf++) {
                const float* p = bA + mf * 16 * LDS_STRIDE + kb;
                af[mf][0] = __float_as_uint(p[0]);
                af[mf][1] = __float_as_uint(p[8 * LDS_STRIDE]);
                af[mf][2] = __float_as_uint(p[4]);
                af[mf][3] = __float_as_uint(p[8 * LDS_STRIDE + 4]);
            }
#pragma unroll
            for (int nf = 0; nf < 4; nf++) {
                const float* p = bB + nf * 8 * LDS_STRIDE + kb;
                bf[nf][0] = __float_as_uint(p[0]);
                bf[nf][1] = __float_as_uint(p[4]);
            }
#pragma unroll
            for (int mf = 0; mf < 4; mf++)
#pragma unroll
                for (int nf = 0; nf < 4; nf++)
                    mma_tf32(acc[mf][nf], af[mf], bf[nf]);
        }
        if (ch + 1 < nch) stsAB((ch + 1) & 1);
        __syncthreads();
    }

    // ---- epilogue ----
#pragma unroll
    for (int mf = 0; mf < 4; mf++) {
        const int lr0 = wm * 64 + mf * 16 + r;   // local row (0..127)
        const int lr1 = lr0 + 8;
        const int row0 = m0 + lr0;
        const int row1 = m0 + lr1;
        int sidx0 = 0, sidx1 = 0;
        if (SCATTER_) { sidx0 = sIdx[lr0]; sidx1 = sIdx[lr1]; }
#pragma unroll
        for (int nf = 0; nf < 4; nf++) {
            const int lc = wn * 32 + nf * 8 + c * 2;  // local col
            const int n = n0 + lc;
#pragma unroll
            for (int half = 0; half < 2; half++) {
                const int row = half ? row1 : row0;
                const int sidx = half ? sidx1 : sidx0;
                if (row >= M) continue;
#pragma unroll
                for (int jj = 0; jj < 2; jj++) {
                    const int nn = n + jj;
                    if (nn >= N) continue;
                    float v = acc[mf][nf][half * 2 + jj] + sbias[lc + jj];
                    if (SILU_) v = silu_f(v);
                    if (RESID_) v += resid[(size_t)row * DD + nn];
                    if (STORE_) C[(size_t)row * N + nn] = v;
                    if (SCATTER_) atomicAdd(&scat[(size_t)sidx * DD + nn], v);
                }
            }
        }
    }
}

// ======================= host =======================
extern "C" void kernel_launch(void* const* d_in, const int* in_sizes, int n_in,
                              void* d_out, int out_size) {
    const float* mesh    = (const float*)d_in[0];
    const float* grid    = (const float*)d_in[1];
    const float* attrs   = (const float*)d_in[2];
    const int*   esrc    = (const int*)d_in[3];
    const int*   edst    = (const int*)d_in[4];
    const float* emb_w0  = (const float*)d_in[5];
    const float* emb_b0  = (const float*)d_in[6];
    const float* emb_w1  = (const float*)d_in[7];
    const float* emb_b1  = (const float*)d_in[8];
    const float* edge_w0 = (const float*)d_in[9];
    const float* edge_b0 = (const float*)d_in[10];
    const float* edge_w1 = (const float*)d_in[11];
    const float* edge_b1 = (const float*)d_in[12];
    const float* node_w0 = (const float*)d_in[13];
    const float* node_b0 = (const float*)d_in[14];
    const float* node_w1 = (const float*)d_in[15];
    const float* node_b1 = (const float*)d_in[16];
    const float* out_w0  = (const float*)d_in[17];
    const float* out_b0  = (const float*)d_in[18];
    const float* out_w1  = (const float*)d_in[19];
    const float* out_b1  = (const float*)d_in[20];
    float* out = (float*)d_out;

    float *ge, *gh, *gagg, *gnh, *ggrid2, *goh, *gwt;
    cudaGetSymbolAddress((void**)&ge, g_e);
    cudaGetSymbolAddress((void**)&gh, g_h);
    cudaGetSymbolAddress((void**)&gagg, g_agg);
    cudaGetSymbolAddress((void**)&gnh, g_nh);
    cudaGetSymbolAddress((void**)&ggrid2, g_grid2);
    cudaGetSymbolAddress((void**)&goh, g_oh);
    cudaGetSymbolAddress((void**)&gwt, g_wt);

    cudaFuncSetAttribute(k_mma<0, false, false, false, true>, cudaFuncAttributeMaxDynamicSharedMemorySize, SMEM_BYTES);
    cudaFuncSetAttribute(k_mma<0, true,  false, false, true>, cudaFuncAttributeMaxDynamicSharedMemorySize, SMEM_BYTES);
    cudaFuncSetAttribute(k_mma<0, false, true,  true,  false>, cudaFuncAttributeMaxDynamicSharedMemorySize, SMEM_BYTES);
    cudaFuncSetAttribute(k_mma<0, false, true,  false, true>, cudaFuncAttributeMaxDynamicSharedMemorySize, SMEM_BYTES);
    cudaFuncSetAttribute(k_mma<1, true,  false, false, true>, cudaFuncAttributeMaxDynamicSharedMemorySize, SMEM_BYTES);
    cudaFuncSetAttribute(k_mma<2, true,  false, false, true>, cudaFuncAttributeMaxDynamicSharedMemorySize, SMEM_BYTES);

    // ---- pre-transpose weights (tf32-rounded) ----
    dim3 tb(32, 8);
    k_transpose<<<dim3(16, 16), tb>>>(emb_w1,  gwt + WT_EMB1,  DD, DD);
    k_transpose<<<dim3(48, 16), tb>>>(edge_w0, gwt + WT_EDGE0, 3 * DD, DD);
    k_transpose<<<dim3(16, 16), tb>>>(edge_w1, gwt + WT_EDGE1, DD, DD);
    k_transpose<<<dim3(32, 16), tb>>>(node_w0, gwt + WT_NODE0, 2 * DD, DD);
    k_transpose<<<dim3(16, 16), tb>>>(node_w1, gwt + WT_NODE1, DD, DD);
    k_transpose<<<dim3(16, 16), tb>>>(out_w0,  gwt + WT_OUT0,  DD, DD);
    k_transpose<<<dim3(16, 15), tb>>>(out_w1,  gwt + WT_OUT1,  DD, OUTD);

    const int TE = (NEDGES + MT - 1) / MT;  // 1528
    const int TG = (NGRID + MT - 1) / MT;   // 510
    const int CN = (DD + NT - 1) / NT;      // 4
    const int CO = (OUTD + NT - 1) / NT;    // 4

    // 1) emb L1 (fp32 exact)
    {
        long long n = (long long)NEDGES * DD;
        k_emb_l1<<<(unsigned)((n + 255) / 256), 256>>>(attrs, emb_w0, emb_b0);
    }
    // 2) emb L2: g_e = g_h @ emb_w1 + b1
    k_mma<0, false, false, false, true><<<dim3(TE, CN), THREADS, SMEM_BYTES>>>(
        gh, nullptr, nullptr, nullptr, nullptr, gwt + WT_EMB1, emb_b1,
        nullptr, ge, nullptr, nullptr, NEDGES, DD, DD);
    // 3) zero agg
    k_zero<<<2048, 256>>>(gagg, (long long)NGRID * DD);
    // 4) edge L1 (fused gather-concat)
    k_mma<1, true, false, false, true><<<dim3(TE, CN), THREADS, SMEM_BYTES>>>(
        mesh, grid, ge, esrc, edst, gwt + WT_EDGE0, edge_b0,
        nullptr, gh, nullptr, nullptr, NEDGES, DD, 3 * DD);
    // 5) edge L2 + residual + fused scatter
    k_mma<0, false, true, true, false><<<dim3(TE, CN), THREADS, SMEM_BYTES>>>(
        gh, nullptr, nullptr, nullptr, nullptr, gwt + WT_EDGE1, edge_b1,
        ge, nullptr, gagg, edst, NEDGES, DD, DD);
    // 6) node L1
    k_mma<2, true, false, false, true><<<dim3(TG, CN), THREADS, SMEM_BYTES>>>(
        grid, gagg, nullptr, nullptr, nullptr, gwt + WT_NODE0, node_b0,
        nullptr, gnh, nullptr, nullptr, NGRID, DD, 2 * DD);
    // 7) node L2 + residual
    k_mma<0, false, true, false, true><<<dim3(TG, CN), THREADS, SMEM_BYTES>>>(
        gnh, nullptr, nullptr, nullptr, nullptr, gwt + WT_NODE1, node_b1,
        grid, ggrid2, nullptr, nullptr, NGRID, DD, DD);
    // 8) out L1
    k_mma<0, true, false, false, true><<<dim3(TG, CN), THREADS, SMEM_BYTES>>>(
        ggrid2, nullptr, nullptr, nullptr, nullptr, gwt + WT_OUT0, out_b0,
        nullptr, goh, nullptr, nullptr, NGRID, DD, DD);
    // 9) out L2 (N=471)
    k_mma<0, false, false, false, true><<<dim3(TG, CO), THREADS, SMEM_BYTES>>>(
        goh, nullptr, nullptr, nullptr, nullptr, gwt + WT_OUT1, out_b1,
        nullptr, out, nullptr, nullptr, NGRID, OUTD, DD);
}

// round 9
// speedup vs baseline: 4.7465x; 1.3559x over previous
#include <cuda_runtime.h>
#include <cuda_fp16.h>
#include <cstdint>

#define NMESH 10242
#define NGRID 65160
#define NEDGES 195480
#define DD 512
#define OUTD 471

#define THREADS 256
#define MT 128          // CTA M tile
#define NT 128          // CTA N tile
#define KCH 32          // K chunk
#define HSTRIDE 40      // smem row stride in fp16 units

// ---- smem layout (bytes) ----
#define SA_OFF 0                      // 2 * 128*40*2 = 20480
#define SB_OFF 20480                  // 2 * 128*40*2 = 20480
#define SBIAS_OFF 40960               // 128 floats = 512
#define SI0_OFF 41472                 // 128 ints
#define SI1_OFF 41984
#define SIDX_OFF 42496
#define SMEM_BYTES 43008

// ---- scratch ----
__device__ float g_e[(size_t)NEDGES * DD];
__device__ float g_h[(size_t)NEDGES * DD];
__device__ float g_agg[(size_t)NGRID * DD];
__device__ float g_nh[(size_t)NGRID * DD];
__device__ float g_grid2[(size_t)NGRID * DD];
__device__ float g_oh[(size_t)NGRID * DD];
__device__ __half g_wh[2600448];

#define WT_EMB1   0
#define WT_EDGE0  262144
#define WT_EDGE1  1048576
#define WT_NODE0  1310720
#define WT_NODE1  1835008
#define WT_OUT0   2097152
#define WT_OUT1   2359296

__device__ __forceinline__ float silu_f(float v) { return v / (1.0f + __expf(-v)); }

__device__ __forceinline__ void mma_f16(float (&d)[4], const uint32_t (&a)[4],
                                        const uint32_t (&b)[2]) {
    asm volatile(
        "mma.sync.aligned.m16n8k16.row.col.f32.f16.f16.f32 "
        "{%0,%1,%2,%3}, {%4,%5,%6,%7}, {%8,%9}, {%0,%1,%2,%3};"
        : "+f"(d[0]), "+f"(d[1]), "+f"(d[2]), "+f"(d[3])
        : "r"(a[0]), "r"(a[1]), "r"(a[2]), "r"(a[3]), "r"(b[0]), "r"(b[1]));
}

// ======================= small kernels =======================
__global__ void k_emb_l1(const float* __restrict__ attrs,
                         const float* __restrict__ w0,
                         const float* __restrict__ b0) {
    long long idx = (long long)blockIdx.x * blockDim.x + threadIdx.x;
    if (idx >= (long long)NEDGES * DD) return;
    int i = (int)(idx / DD);
    int j = (int)(idx % DD);
    float v = b0[j];
    v += attrs[i * 4 + 0] * w0[0 * DD + j];
    v += attrs[i * 4 + 1] * w0[1 * DD + j];
    v += attrs[i * 4 + 2] * w0[2 * DD + j];
    v += attrs[i * 4 + 3] * w0[3 * DD + j];
    g_h[idx] = silu_f(v);
}

__global__ void k_zero(float* __restrict__ p, long long n) {
    long long i = (long long)blockIdx.x * blockDim.x + threadIdx.x;
    long long stride = (long long)gridDim.x * blockDim.x;
    for (; i < n; i += stride) p[i] = 0.0f;
}

// Wh[n][k] = fp16(W[k][n])
__global__ void k_transpose(const float* __restrict__ in, __half* __restrict__ out,
                            int K, int N) {
    __shared__ float t[32][33];
    int k0 = blockIdx.x * 32, n0 = blockIdx.y * 32;
#pragma unroll
    for (int i = 0; i < 4; i++) {
        int k = k0 + threadIdx.y + i * 8;
        int n = n0 + threadIdx.x;
        t[threadIdx.y + i * 8][threadIdx.x] = (k < K && n < N) ? in[(size_t)k * N + n] : 0.f;
    }
    __syncthreads();
#pragma unroll
    for (int i = 0; i < 4; i++) {
        int n = n0 + threadIdx.y + i * 8;
        int k = k0 + threadIdx.x;
        if (n < N && k < K)
            out[(size_t)n * K + k] = __float2half_rn(t[threadIdx.x][threadIdx.y + i * 8]);
    }
}

// ======================= fp16 mma.sync GEMM =======================
// C[M,N] = epi(A @ W + bias). AMODE 0: plain; 1: gather-concat
// [A0[gidx0]|A1[gidx1]|A2] K=1536; 2: concat [A0|A1] K=1024.
// Wh pre-transposed [N][K] fp16. CTA 128x128, 8 warps (2x4), warp 64x32.
template <int AMODE, bool SILU_, bool RESID_, bool SCATTER_, bool STORE_>
__global__ void __launch_bounds__(THREADS)
k_mma(const float* __restrict__ A0, const float* __restrict__ A1,
      const float* __restrict__ A2,
      const int* __restrict__ gidx0, const int* __restrict__ gidx1,
      const __half* __restrict__ Wh, const float* __restrict__ bias,
      const float* __restrict__ resid,
      float* __restrict__ C,
      float* __restrict__ scat, const int* __restrict__ scat_idx,
      int M, int N, int K) {
    extern __shared__ char smraw[];
    __half* sA = (__half*)(smraw + SA_OFF);
    __half* sB = (__half*)(smraw + SB_OFF);
    float* sbias = (float*)(smraw + SBIAS_OFF);
    int* sI0 = (int*)(smraw + SI0_OFF);
    int* sI1 = (int*)(smraw + SI1_OFF);
    int* sIdx = (int*)(smraw + SIDX_OFF);

    const int tid = threadIdx.x;
    const int lane = tid & 31;
    const int wid = tid >> 5;
    const int m0 = blockIdx.x * MT;
    const int n0 = blockIdx.y * NT;

    if (tid < 128) {
        sbias[tid] = (n0 + tid < N) ? bias[n0 + tid] : 0.0f;
        int gr = m0 + tid; if (gr >= M) gr = M - 1;
        if (AMODE == 1) { sI0[tid] = gidx0[gr]; sI1[tid] = gidx1[gr]; }
        if (SCATTER_) sIdx[tid] = scat_idx[gr];
    }
    __syncthreads();

    // A loader: rows tid>>3 (+32*j), 4 floats each (q = tid&7)
    const int arow = tid >> 3;        // 0..31
    const int aq = tid & 7;           // 0..7 : unit of 4 floats
    // B loader: rows tid>>2 (+64*j), 8 fp16 each (u = tid&3)
    const int brow = tid >> 2;        // 0..63
    const int bu = tid & 3;           // 0..3

    float4 ra[4];
    uint4 rbv[2];

    auto loadA = [&](int kc0) {
#pragma unroll
        for (int j = 0; j < 4; j++) {
            int row = arow + j * 32;
            int gr = m0 + row; if (gr >= M) gr = M - 1;
            const float* src;
            if (AMODE == 0) {
                src = A0 + (size_t)gr * K + kc0;
            } else if (AMODE == 1) {
                if (kc0 < DD)          src = A0 + (size_t)sI0[row] * DD + kc0;
                else if (kc0 < 2 * DD) src = A1 + (size_t)sI1[row] * DD + (kc0 - DD);
                else                   src = A2 + (size_t)gr * DD + (kc0 - 2 * DD);
            } else {
                if (kc0 < DD) src = A0 + (size_t)gr * DD + kc0;
                else          src = A1 + (size_t)gr * DD + (kc0 - DD);
            }
            ra[j] = *(const float4*)(src + aq * 4);
        }
    };
    auto loadB = [&](int kc0) {
#pragma unroll
        for (int j = 0; j < 2; j++) {
            int row = brow + j * 64;
            int n = n0 + row;
            if (n < N) rbv[j] = *(const uint4*)(Wh + (size_t)n * K + kc0 + bu * 8);
            else       rbv[j] = make_uint4(0, 0, 0, 0);
        }
    };
    auto stsAB = [&](int buf) {
        __half* dA = sA + buf * (128 * HSTRIDE);
        __half* dB = sB + buf * (128 * HSTRIDE);
#pragma unroll
        for (int j = 0; j < 4; j++) {
            int row = arow + j * 32;
            float4 v = ra[j];
            __half2 h0 = __floats2half2_rn(v.x, v.y);
            __half2 h1 = __floats2half2_rn(v.z, v.w);
            uint2 o = make_uint2(*(uint32_t*)&h0, *(uint32_t*)&h1);
            *(uint2*)(dA + row * HSTRIDE + aq * 4) = o;
        }
#pragma unroll
        for (int j = 0; j < 2; j++) {
            int row = brow + j * 64;
            *(uint4*)(dB + row * HSTRIDE + bu * 8) = rbv[j];
        }
    };

    float acc[4][4][4] = {};
    const int wm = wid >> 2;          // 0..1
    const int wn = wid & 3;           // 0..3
    const int r = lane >> 2;          // 0..7
    const int c = lane & 3;           // 0..3

    const int nch = K / KCH;
    loadA(0); loadB(0);
    stsAB(0);
    __syncthreads();

    for (int ch = 0; ch < nch; ch++) {
        const int buf = ch & 1;
        if (ch + 1 < nch) { loadA((ch + 1) * KCH); loadB((ch + 1) * KCH); }

        const __half* bA = sA + buf * (128 * HSTRIDE) + (wm * 64 + r) * HSTRIDE + 2 * c;
        const __half* bB = sB + buf * (128 * HSTRIDE) + (wn * 32 + r) * HSTRIDE + 2 * c;
#pragma unroll
        for (int kk = 0; kk < 2; kk++) {
            const int kb = kk * 16;
            uint32_t af[4][4], bf[4][2];
#pragma unroll
            for (int mf = 0; mf < 4; mf++) {
                const __half* p = bA + mf * 16 * HSTRIDE + kb;
                af[mf][0] = *(const uint32_t*)(p);
                af[mf][1] = *(const uint32_t*)(p + 8 * HSTRIDE);
                af[mf][2] = *(const uint32_t*)(p + 8);
                af[mf][3] = *(const uint32_t*)(p + 8 * HSTRIDE + 8);
            }
#pragma unroll
            for (int nf = 0; nf < 4; nf++) {
                const __half* p = bB + nf * 8 * HSTRIDE + kb;
                bf[nf][0] = *(const uint32_t*)(p);
                bf[nf][1] = *(const uint32_t*)(p + 8);
            }
#pragma unroll
            for (int mf = 0; mf < 4; mf++)
#pragma unroll
                for (int nf = 0; nf < 4; nf++)
                    mma_f16(acc[mf][nf], af[mf], bf[nf]);
        }
        if (ch + 1 < nch) stsAB((ch + 1) & 1);
        __syncthreads();
    }

    // ---- epilogue ----
#pragma unroll
    for (int mf = 0; mf < 4; mf++) {
        const int lr0 = wm * 64 + mf * 16 + r;
        const int lr1 = lr0 + 8;
        const int row0 = m0 + lr0;
        const int row1 = m0 + lr1;
        int sidx0 = 0, sidx1 = 0;
        if (SCATTER_) { sidx0 = sIdx[lr0]; sidx1 = sIdx[lr1]; }
#pragma unroll
        for (int nf = 0; nf < 4; nf++) {
            const int lc = wn * 32 + nf * 8 + c * 2;
            const int n = n0 + lc;
#pragma unroll
            for (int half_ = 0; half_ < 2; half_++) {
                const int row = half_ ? row1 : row0;
                const int sidx = half_ ? sidx1 : sidx0;
                if (row >= M) continue;
#pragma unroll
                for (int jj = 0; jj < 2; jj++) {
                    const int nn = n + jj;
                    if (nn >= N) continue;
                    float v = acc[mf][nf][half_ * 2 + jj] + sbias[lc + jj];
                    if (SILU_) v = silu_f(v);
                    if (RESID_) v += resid[(size_t)row * DD + nn];
                    if (STORE_) C[(size_t)row * N + nn] = v;
                    if (SCATTER_) atomicAdd(&scat[(size_t)sidx * DD + nn], v);
                }
            }
        }
    }
}

// ======================= host =======================
extern "C" void kernel_launch(void* const* d_in, const int* in_sizes, int n_in,
                              void* d_out, int out_size) {
    const float* mesh    = (const float*)d_in[0];
    const float* grid    = (const float*)d_in[1];
    const float* attrs   = (const float*)d_in[2];
    const int*   esrc    = (const int*)d_in[3];
    const int*   edst    = (const int*)d_in[4];
    const float* emb_w0  = (const float*)d_in[5];
    const float* emb_b0  = (const float*)d_in[6];
    const float* emb_w1  = (const float*)d_in[7];
    const float* emb_b1  = (const float*)d_in[8];
    const float* edge_w0 = (const float*)d_in[9];
    const float* edge_b0 = (const float*)d_in[10];
    const float* edge_w1 = (const float*)d_in[11];
    const float* edge_b1 = (const float*)d_in[12];
    const float* node_w0 = (const float*)d_in[13];
    const float* node_b0 = (const float*)d_in[14];
    const float* node_w1 = (const float*)d_in[15];
    const float* node_b1 = (const float*)d_in[16];
    const float* out_w0  = (const float*)d_in[17];
    const float* out_b0  = (const float*)d_in[18];
    const float* out_w1  = (const float*)d_in[19];
    const float* out_b1  = (const float*)d_in[20];
    float* out = (float*)d_out;

    float *ge, *gh, *gagg, *gnh, *ggrid2, *goh;
    __half* gwh;
    cudaGetSymbolAddress((void**)&ge, g_e);
    cudaGetSymbolAddress((void**)&gh, g_h);
    cudaGetSymbolAddress((void**)&gagg, g_agg);
    cudaGetSymbolAddress((void**)&gnh, g_nh);
    cudaGetSymbolAddress((void**)&ggrid2, g_grid2);
    cudaGetSymbolAddress((void**)&goh, g_oh);
    cudaGetSymbolAddress((void**)&gwh, g_wh);

    cudaFuncSetAttribute(k_mma<0, false, false, false, true>, cudaFuncAttributeMaxDynamicSharedMemorySize, SMEM_BYTES);
    cudaFuncSetAttribute(k_mma<0, true,  false, false, true>, cudaFuncAttributeMaxDynamicSharedMemorySize, SMEM_BYTES);
    cudaFuncSetAttribute(k_mma<0, false, true,  true,  false>, cudaFuncAttributeMaxDynamicSharedMemorySize, SMEM_BYTES);
    cudaFuncSetAttribute(k_mma<0, false, true,  false, true>, cudaFuncAttributeMaxDynamicSharedMemorySize, SMEM_BYTES);
    cudaFuncSetAttribute(k_mma<1, true,  false, false, true>, cudaFuncAttributeMaxDynamicSharedMemorySize, SMEM_BYTES);
    cudaFuncSetAttribute(k_mma<2, true,  false, false, true>, cudaFuncAttributeMaxDynamicSharedMemorySize, SMEM_BYTES);

    // ---- pre-transpose weights to fp16 ----
    dim3 tb(32, 8);
    k_transpose<<<dim3(16, 16), tb>>>(emb_w1,  gwh + WT_EMB1,  DD, DD);
    k_transpose<<<dim3(48, 16), tb>>>(edge_w0, gwh + WT_EDGE0, 3 * DD, DD);
    k_transpose<<<dim3(16, 16), tb>>>(edge_w1, gwh + WT_EDGE1, DD, DD);
    k_transpose<<<dim3(32, 16), tb>>>(node_w0, gwh + WT_NODE0, 2 * DD, DD);
    k_transpose<<<dim3(16, 16), tb>>>(node_w1, gwh + WT_NODE1, DD, DD);
    k_transpose<<<dim3(16, 16), tb>>>(out_w0,  gwh + WT_OUT0,  DD, DD);
    k_transpose<<<dim3(16, 15), tb>>>(out_w1,  gwh + WT_OUT1,  DD, OUTD);

    const int TE = (NEDGES + MT - 1) / MT;  // 1528
    const int TG = (NGRID + MT - 1) / MT;   // 510
    const int CN = (DD + NT - 1) / NT;      // 4
    const int CO = (OUTD + NT - 1) / NT;    // 4

    // 1) emb L1 (fp32 exact)
    {
        long long n = (long long)NEDGES * DD;
        k_emb_l1<<<(unsigned)((n + 255) / 256), 256>>>(attrs, emb_w0, emb_b0);
    }
    // 2) emb L2: g_e = g_h @ emb_w1 + b1
    k_mma<0, false, false, false, true><<<dim3(TE, CN), THREADS, SMEM_BYTES>>>(
        gh, nullptr, nullptr, nullptr, nullptr, gwh + WT_EMB1, emb_b1,
        nullptr, ge, nullptr, nullptr, NEDGES, DD, DD);
    // 3) zero agg
    k_zero<<<2048, 256>>>(gagg, (long long)NGRID * DD);
    // 4) edge L1 (fused gather-concat)
    k_mma<1, true, false, false, true><<<dim3(TE, CN), THREADS, SMEM_BYTES>>>(
        mesh, grid, ge, esrc, edst, gwh + WT_EDGE0, edge_b0,
        nullptr, gh, nullptr, nullptr, NEDGES, DD, 3 * DD);
    // 5) edge L2 + residual + fused scatter
    k_mma<0, false, true, true, false><<<dim3(TE, CN), THREADS, SMEM_BYTES>>>(
        gh, nullptr, nullptr, nullptr, nullptr, gwh + WT_EDGE1, edge_b1,
        ge, nullptr, gagg, edst, NEDGES, DD, DD);
    // 6) node L1
    k_mma<2, true, false, false, true><<<dim3(TG, CN), THREADS, SMEM_BYTES>>>(
        grid, gagg, nullptr, nullptr, nullptr, gwh + WT_NODE0, node_b0,
        nullptr, gnh, nullptr, nullptr, NGRID, DD, 2 * DD);
    // 7) node L2 + residual
    k_mma<0, false, true, false, true><<<dim3(TG, CN), THREADS, SMEM_BYTES>>>(
        gnh, nullptr, nullptr, nullptr, nullptr, gwh + WT_NODE1, node_b1,
        grid, ggrid2, nullptr, nullptr, NGRID, DD, DD);
    // 8) out L1
    k_mma<0, true, false, false, true><<<dim3(TG, CN), THREADS, SMEM_BYTES>>>(
        ggrid2, nullptr, nullptr, nullptr, nullptr, gwh + WT_OUT0, out_b0,
        nullptr, goh, nullptr, nullptr, NGRID, DD, DD);
    // 9) out L2 (N=471)
    k_mma<0, false, false, false, true><<<dim3(TG, CO), THREADS, SMEM_BYTES>>>(
        goh, nullptr, nullptr, nullptr, nullptr, gwh + WT_OUT1, out_b1,
        nullptr, out, nullptr, nullptr, NGRID, OUTD, DD);
}

// round 11
// speedup vs baseline: 6.1892x; 1.3039x over previous
#include <cuda_runtime.h>
#include <cuda_fp16.h>
#include <cstdint>

#define NMESH 10242
#define NGRID 65160
#define NEDGES 195480
#define DD 512
#define OUTD 471

#define THREADS 256
#define MT 128          // CTA M tile
#define NT 128          // CTA N tile
#define KCH 32          // K chunk
#define HSTRIDE 40      // smem row stride in fp16 units

// ---- smem layout (bytes) ----
#define SA_OFF 0                      // 2 * 128*40*2 = 20480
#define SB_OFF 20480                  // 2 * 128*40*2 = 20480
#define SBIAS_OFF 40960               // 128 floats
#define SI0_OFF 41472
#define SI1_OFF 41984
#define SIDX_OFF 42496
#define SMEM_BYTES 43008

// ---- scratch ----
__device__ float g_e[(size_t)NEDGES * DD];
__device__ float g_h[(size_t)NEDGES * DD];
__device__ float g_agg[(size_t)NGRID * DD];
__device__ float g_nh[(size_t)NGRID * DD];
__device__ float g_grid2[(size_t)NGRID * DD];
__device__ float g_oh[(size_t)NGRID * DD];
__device__ __half g_wh[2600448];

#define WT_EMB1   0
#define WT_EDGE0  262144
#define WT_EDGE1  1048576
#define WT_NODE0  1310720
#define WT_NODE1  1835008
#define WT_OUT0   2097152
#define WT_OUT1   2359296

__device__ __forceinline__ float silu_f(float v) { return v / (1.0f + __expf(-v)); }

__device__ __forceinline__ void mma_f16(float (&d)[4], const uint32_t (&a)[4],
                                        const uint32_t (&b)[2]) {
    asm volatile(
        "mma.sync.aligned.m16n8k16.row.col.f32.f16.f16.f32 "
        "{%0,%1,%2,%3}, {%4,%5,%6,%7}, {%8,%9}, {%0,%1,%2,%3};"
        : "+f"(d[0]), "+f"(d[1]), "+f"(d[2]), "+f"(d[3])
        : "r"(a[0]), "r"(a[1]), "r"(a[2]), "r"(a[3]), "r"(b[0]), "r"(b[1]));
}

__device__ __forceinline__ void ldsm_x4(uint32_t (&r)[4], uint32_t addr) {
    asm volatile("ldmatrix.sync.aligned.m8n8.x4.shared.b16 {%0,%1,%2,%3}, [%4];"
        : "=r"(r[0]), "=r"(r[1]), "=r"(r[2]), "=r"(r[3]) : "r"(addr));
}

// ======================= small kernels =======================
__global__ void k_emb_l1(const float* __restrict__ attrs,
                         const float* __restrict__ w0,
                         const float* __restrict__ b0) {
    long long idx = (long long)blockIdx.x * blockDim.x + threadIdx.x;
    if (idx >= (long long)NEDGES * DD) return;
    int i = (int)(idx / DD);
    int j = (int)(idx % DD);
    float v = b0[j];
    v += attrs[i * 4 + 0] * w0[0 * DD + j];
    v += attrs[i * 4 + 1] * w0[1 * DD + j];
    v += attrs[i * 4 + 2] * w0[2 * DD + j];
    v += attrs[i * 4 + 3] * w0[3 * DD + j];
    g_h[idx] = silu_f(v);
}

__global__ void k_zero(float* __restrict__ p, long long n) {
    long long i = (long long)blockIdx.x * blockDim.x + threadIdx.x;
    long long stride = (long long)gridDim.x * blockDim.x;
    for (; i < n; i += stride) p[i] = 0.0f;
}

// Wh[n][k] = fp16(W[k][n])
__global__ void k_transpose(const float* __restrict__ in, __half* __restrict__ out,
                            int K, int N) {
    __shared__ float t[32][33];
    int k0 = blockIdx.x * 32, n0 = blockIdx.y * 32;
#pragma unroll
    for (int i = 0; i < 4; i++) {
        int k = k0 + threadIdx.y + i * 8;
        int n = n0 + threadIdx.x;
        t[threadIdx.y + i * 8][threadIdx.x] = (k < K && n < N) ? in[(size_t)k * N + n] : 0.f;
    }
    __syncthreads();
#pragma unroll
    for (int i = 0; i < 4; i++) {
        int n = n0 + threadIdx.y + i * 8;
        int k = k0 + threadIdx.x;
        if (n < N && k < K)
            out[(size_t)n * K + k] = __float2half_rn(t[threadIdx.x][threadIdx.y + i * 8]);
    }
}

// ======================= fp16 mma.sync GEMM (ldmatrix frags) =======================
template <int AMODE, bool SILU_, bool RESID_, bool SCATTER_, bool STORE_>
__global__ void __launch_bounds__(THREADS)
k_mma(const float* __restrict__ A0, const float* __restrict__ A1,
      const float* __restrict__ A2,
      const int* __restrict__ gidx0, const int* __restrict__ gidx1,
      const __half* __restrict__ Wh, const float* __restrict__ bias,
      const float* __restrict__ resid,
      float* __restrict__ C,
      float* __restrict__ scat, const int* __restrict__ scat_idx,
      int M, int N, int K) {
    extern __shared__ char smraw[];
    __half* sA = (__half*)(smraw + SA_OFF);
    __half* sB = (__half*)(smraw + SB_OFF);
    float* sbias = (float*)(smraw + SBIAS_OFF);
    int* sI0 = (int*)(smraw + SI0_OFF);
    int* sI1 = (int*)(smraw + SI1_OFF);
    int* sIdx = (int*)(smraw + SIDX_OFF);

    const int tid = threadIdx.x;
    const int lane = tid & 31;
    const int wid = tid >> 5;
    const int m0 = blockIdx.x * MT;
    const int n0 = blockIdx.y * NT;

    if (tid < 128) {
        sbias[tid] = (n0 + tid < N) ? bias[n0 + tid] : 0.0f;
        int gr = m0 + tid; if (gr >= M) gr = M - 1;
        if (AMODE == 1) { sI0[tid] = gidx0[gr]; sI1[tid] = gidx1[gr]; }
        if (SCATTER_) sIdx[tid] = scat_idx[gr];
    }
    __syncthreads();

    const int arow = tid >> 3;        // 0..31
    const int aq = tid & 7;           // 0..7
    const int brow = tid >> 2;        // 0..63
    const int bu = tid & 3;           // 0..3

    float4 ra[4];
    uint4 rbv[2];

    auto loadA = [&](int kc0) {
#pragma unroll
        for (int j = 0; j < 4; j++) {
            int row = arow + j * 32;
            int gr = m0 + row; if (gr >= M) gr = M - 1;
            const float* src;
            if (AMODE == 0) {
                src = A0 + (size_t)gr * K + kc0;
            } else if (AMODE == 1) {
                if (kc0 < DD)          src = A0 + (size_t)sI0[row] * DD + kc0;
                else if (kc0 < 2 * DD) src = A1 + (size_t)sI1[row] * DD + (kc0 - DD);
                else                   src = A2 + (size_t)gr * DD + (kc0 - 2 * DD);
            } else {
                if (kc0 < DD) src = A0 + (size_t)gr * DD + kc0;
                else          src = A1 + (size_t)gr * DD + (kc0 - DD);
            }
            ra[j] = *(const float4*)(src + aq * 4);
        }
    };
    auto loadB = [&](int kc0) {
#pragma unroll
        for (int j = 0; j < 2; j++) {
            int row = brow + j * 64;
            int n = n0 + row;
            if (n < N) rbv[j] = *(const uint4*)(Wh + (size_t)n * K + kc0 + bu * 8);
            else       rbv[j] = make_uint4(0, 0, 0, 0);
        }
    };
    auto stsAB = [&](int buf) {
        __half* dA = sA + buf * (128 * HSTRIDE);
        __half* dB = sB + buf * (128 * HSTRIDE);
#pragma unroll
        for (int j = 0; j < 4; j++) {
            int row = arow + j * 32;
            float4 v = ra[j];
            __half2 h0 = __floats2half2_rn(v.x, v.y);
            __half2 h1 = __floats2half2_rn(v.z, v.w);
            uint2 o = make_uint2(*(uint32_t*)&h0, *(uint32_t*)&h1);
            *(uint2*)(dA + row * HSTRIDE + aq * 4) = o;
        }
#pragma unroll
        for (int j = 0; j < 2; j++) {
            int row = brow + j * 64;
            *(uint4*)(dB + row * HSTRIDE + bu * 8) = rbv[j];
        }
    };

    float acc[4][4][4] = {};
    const int wm = wid >> 2;          // 0..1
    const int wn = wid & 3;           // 0..3
    const int r = lane >> 2;          // 0..7
    const int c = lane & 3;           // 0..3

    // ---- ldmatrix lane base offsets (in halves, relative to buffer base) ----
    // A x4: lanes 0-15 -> rows 0-15 @k, lanes 16-31 -> rows 0-15 @k+8
    const uint32_t a_lane_off = (uint32_t)((wm * 64 + (lane & 15)) * HSTRIDE + ((lane >> 4) & 1) * 8);
    // B x4 (covers n-frag pair 2g,2g+1): lane bit3 -> k+8, bit4 -> n+8
    const uint32_t b_lane_off = (uint32_t)((wn * 32 + ((lane >> 4) & 1) * 8 + (lane & 7)) * HSTRIDE
                                           + ((lane >> 3) & 1) * 8);
    const uint32_t sA_u32 = (uint32_t)__cvta_generic_to_shared(sA);
    const uint32_t sB_u32 = (uint32_t)__cvta_generic_to_shared(sB);

    const int nch = K / KCH;
    loadA(0); loadB(0);
    stsAB(0);
    __syncthreads();

    for (int ch = 0; ch < nch; ch++) {
        const int buf = ch & 1;
        if (ch + 1 < nch) { loadA((ch + 1) * KCH); loadB((ch + 1) * KCH); }

        const uint32_t aBase = sA_u32 + (buf * (128 * HSTRIDE) + a_lane_off) * 2;
        const uint32_t bBase = sB_u32 + (buf * (128 * HSTRIDE) + b_lane_off) * 2;
#pragma unroll
        for (int kk = 0; kk < 2; kk++) {
            const int kb = kk * 16;
            uint32_t af[4][4], bf[4][2];
#pragma unroll
            for (int mf = 0; mf < 4; mf++)
                ldsm_x4(af[mf], aBase + (mf * 16 * HSTRIDE + kb) * 2);
#pragma unroll
            for (int g = 0; g < 2; g++) {
                uint32_t bq[4];
                ldsm_x4(bq, bBase + (g * 16 * HSTRIDE + kb) * 2);
                bf[2 * g][0] = bq[0]; bf[2 * g][1] = bq[1];
                bf[2 * g + 1][0] = bq[2]; bf[2 * g + 1][1] = bq[3];
            }
#pragma unroll
            for (int mf = 0; mf < 4; mf++)
#pragma unroll
                for (int nf = 0; nf < 4; nf++)
                    mma_f16(acc[mf][nf], af[mf], bf[nf]);
        }
        if (ch + 1 < nch) stsAB((ch + 1) & 1);
        __syncthreads();
    }

    // ---- epilogue ----
#pragma unroll
    for (int mf = 0; mf < 4; mf++) {
        const int lr0 = wm * 64 + mf * 16 + r;
        const int lr1 = lr0 + 8;
        const int row0 = m0 + lr0;
        const int row1 = m0 + lr1;
        int sidx0 = 0, sidx1 = 0;
        if (SCATTER_) { sidx0 = sIdx[lr0]; sidx1 = sIdx[lr1]; }
#pragma unroll
        for (int nf = 0; nf < 4; nf++) {
            const int lc = wn * 32 + nf * 8 + c * 2;
            const int n = n0 + lc;
#pragma unroll
            for (int half_ = 0; half_ < 2; half_++) {
                const int row = half_ ? row1 : row0;
                const int sidx = half_ ? sidx1 : sidx0;
                if (row >= M) continue;
#pragma unroll
                for (int jj = 0; jj < 2; jj++) {
                    const int nn = n + jj;
                    if (nn >= N) continue;
                    float v = acc[mf][nf][half_ * 2 + jj] + sbias[lc + jj];
                    if (SILU_) v = silu_f(v);
                    if (RESID_) v += resid[(size_t)row * DD + nn];
                    if (STORE_) C[(size_t)row * N + nn] = v;
                    if (SCATTER_) atomicAdd(&scat[(size_t)sidx * DD + nn], v);
                }
            }
        }
    }
}

// ======================= host =======================
extern "C" void kernel_launch(void* const* d_in, const int* in_sizes, int n_in,
                              void* d_out, int out_size) {
    const float* mesh    = (const float*)d_in[0];
    const float* grid    = (const float*)d_in[1];
    const float* attrs   = (const float*)d_in[2];
    const int*   esrc    = (const int*)d_in[3];
    const int*   edst    = (const int*)d_in[4];
    const float* emb_w0  = (const float*)d_in[5];
    const float* emb_b0  = (const float*)d_in[6];
    const float* emb_w1  = (const float*)d_in[7];
    const float* emb_b1  = (const float*)d_in[8];
    const float* edge_w0 = (const float*)d_in[9];
    const float* edge_b0 = (const float*)d_in[10];
    const float* edge_w1 = (const float*)d_in[11];
    const float* edge_b1 = (const float*)d_in[12];
    const float* node_w0 = (const float*)d_in[13];
    const float* node_b0 = (const float*)d_in[14];
    const float* node_w1 = (const float*)d_in[15];
    const float* node_b1 = (const float*)d_in[16];
    const float* out_w0  = (const float*)d_in[17];
    const float* out_b0  = (const float*)d_in[18];
    const float* out_w1  = (const float*)d_in[19];
    const float* out_b1  = (const float*)d_in[20];
    float* out = (float*)d_out;

    float *ge, *gh, *gagg, *gnh, *ggrid2, *goh;
    __half* gwh;
    cudaGetSymbolAddress((void**)&ge, g_e);
    cudaGetSymbolAddress((void**)&gh, g_h);
    cudaGetSymbolAddress((void**)&gagg, g_agg);
    cudaGetSymbolAddress((void**)&gnh, g_nh);
    cudaGetSymbolAddress((void**)&ggrid2, g_grid2);
    cudaGetSymbolAddress((void**)&goh, g_oh);
    cudaGetSymbolAddress((void**)&gwh, g_wh);

    cudaFuncSetAttribute(k_mma<0, false, false, false, true>, cudaFuncAttributeMaxDynamicSharedMemorySize, SMEM_BYTES);
    cudaFuncSetAttribute(k_mma<0, true,  false, false, true>, cudaFuncAttributeMaxDynamicSharedMemorySize, SMEM_BYTES);
    cudaFuncSetAttribute(k_mma<0, false, true,  true,  false>, cudaFuncAttributeMaxDynamicSharedMemorySize, SMEM_BYTES);
    cudaFuncSetAttribute(k_mma<0, false, true,  false, true>, cudaFuncAttributeMaxDynamicSharedMemorySize, SMEM_BYTES);
    cudaFuncSetAttribute(k_mma<1, true,  false, false, true>, cudaFuncAttributeMaxDynamicSharedMemorySize, SMEM_BYTES);
    cudaFuncSetAttribute(k_mma<2, true,  false, false, true>, cudaFuncAttributeMaxDynamicSharedMemorySize, SMEM_BYTES);

    // ---- pre-transpose weights to fp16 ----
    dim3 tb(32, 8);
    k_transpose<<<dim3(16, 16), tb>>>(emb_w1,  gwh + WT_EMB1,  DD, DD);
    k_transpose<<<dim3(48, 16), tb>>>(edge_w0, gwh + WT_EDGE0, 3 * DD, DD);
    k_transpose<<<dim3(16, 16), tb>>>(edge_w1, gwh + WT_EDGE1, DD, DD);
    k_transpose<<<dim3(32, 16), tb>>>(node_w0, gwh + WT_NODE0, 2 * DD, DD);
    k_transpose<<<dim3(16, 16), tb>>>(node_w1, gwh + WT_NODE1, DD, DD);
    k_transpose<<<dim3(16, 16), tb>>>(out_w0,  gwh + WT_OUT0,  DD, DD);
    k_transpose<<<dim3(16, 15), tb>>>(out_w1,  gwh + WT_OUT1,  DD, OUTD);

    const int TE = (NEDGES + MT - 1) / MT;  // 1528
    const int TG = (NGRID + MT - 1) / MT;   // 510
    const int CN = (DD + NT - 1) / NT;      // 4
    const int CO = (OUTD + NT - 1) / NT;    // 4

    // 1) emb L1 (fp32 exact)
    {
        long long n = (long long)NEDGES * DD;
        k_emb_l1<<<(unsigned)((n + 255) / 256), 256>>>(attrs, emb_w0, emb_b0);
    }
    // 2) emb L2: g_e = g_h @ emb_w1 + b1
    k_mma<0, false, false, false, true><<<dim3(TE, CN), THREADS, SMEM_BYTES>>>(
        gh, nullptr, nullptr, nullptr, nullptr, gwh + WT_EMB1, emb_b1,
        nullptr, ge, nullptr, nullptr, NEDGES, DD, DD);
    // 3) zero agg
    k_zero<<<2048, 256>>>(gagg, (long long)NGRID * DD);
    // 4) edge L1 (fused gather-concat)
    k_mma<1, true, false, false, true><<<dim3(TE, CN), THREADS, SMEM_BYTES>>>(
        mesh, grid, ge, esrc, edst, gwh + WT_EDGE0, edge_b0,
        nullptr, gh, nullptr, nullptr, NEDGES, DD, 3 * DD);
    // 5) edge L2 + residual + fused scatter
    k_mma<0, false, true, true, false><<<dim3(TE, CN), THREADS, SMEM_BYTES>>>(
        gh, nullptr, nullptr, nullptr, nullptr, gwh + WT_EDGE1, edge_b1,
        ge, nullptr, gagg, edst, NEDGES, DD, DD);
    // 6) node L1
    k_mma<2, true, false, false, true><<<dim3(TG, CN), THREADS, SMEM_BYTES>>>(
        grid, gagg, nullptr, nullptr, nullptr, gwh + WT_NODE0, node_b0,
        nullptr, gnh, nullptr, nullptr, NGRID, DD, 2 * DD);
    // 7) node L2 + residual
    k_mma<0, false, true, false, true><<<dim3(TG, CN), THREADS, SMEM_BYTES>>>(
        gnh, nullptr, nullptr, nullptr, nullptr, gwh + WT_NODE1, node_b1,
        grid, ggrid2, nullptr, nullptr, NGRID, DD, DD);
    // 8) out L1
    k_mma<0, true, false, false, true><<<dim3(TG, CN), THREADS, SMEM_BYTES>>>(
        ggrid2, nullptr, nullptr, nullptr, nullptr, gwh + WT_OUT0, out_b0,
        nullptr, goh, nullptr, nullptr, NGRID, DD, DD);
    // 9) out L2 (N=471)
    k_mma<0, false, false, false, true><<<dim3(TG, CO), THREADS, SMEM_BYTES>>>(
        goh, nullptr, nullptr, nullptr, nullptr, gwh + WT_OUT1, out_b1,
        nullptr, out, nullptr, nullptr, NGRID, OUTD, DD);
}

// round 12
// speedup vs baseline: 6.4190x; 1.0371x over previous
#include <cuda_runtime.h>
#include <cuda_fp16.h>
#include <cstdint>

#define NMESH 10242
#define NGRID 65160
#define NEDGES 195480
#define DD 512
#define OUTD 471

#define THREADS 256
#define MT 128
#define NT 128
#define KCH 32
#define HSTRIDE 40      // smem row stride in fp16 units

// ---- smem layout (bytes) ----
#define SA_OFF 0
#define SB_OFF 20480
#define SBIAS_OFF 40960
#define SI0_OFF 41472
#define SI1_OFF 41984
#define SIDX_OFF 42496
#define SMEM_BYTES 43008

// ---- scratch ----
__device__ float  g_e[(size_t)NEDGES * DD];       // fp32 (residual source)
__device__ __half g_h16[(size_t)NEDGES * DD];     // hidden (emb hidden, edge hidden)
__device__ float  g_agg[(size_t)NGRID * DD];      // fp32 (atomic accumulate)
__device__ __half g_nh16[(size_t)NGRID * DD];
__device__ __half g_g2_16[(size_t)NGRID * DD];
__device__ __half g_oh16[(size_t)NGRID * DD];
__device__ __half g_mesh16[(size_t)NMESH * DD];
__device__ __half g_grid16[(size_t)NGRID * DD];
__device__ __half g_wh[2600448];

#define WT_EMB1   0
#define WT_EDGE0  262144
#define WT_EDGE1  1048576
#define WT_NODE0  1310720
#define WT_NODE1  1835008
#define WT_OUT0   2097152
#define WT_OUT1   2359296

__device__ __forceinline__ float silu_f(float v) { return v / (1.0f + __expf(-v)); }

__device__ __forceinline__ void mma_f16(float (&d)[4], const uint32_t (&a)[4],
                                        const uint32_t (&b)[2]) {
    asm volatile(
        "mma.sync.aligned.m16n8k16.row.col.f32.f16.f16.f32 "
        "{%0,%1,%2,%3}, {%4,%5,%6,%7}, {%8,%9}, {%0,%1,%2,%3};"
        : "+f"(d[0]), "+f"(d[1]), "+f"(d[2]), "+f"(d[3])
        : "r"(a[0]), "r"(a[1]), "r"(a[2]), "r"(a[3]), "r"(b[0]), "r"(b[1]));
}

__device__ __forceinline__ void ldsm_x4(uint32_t (&r)[4], uint32_t addr) {
    asm volatile("ldmatrix.sync.aligned.m8n8.x4.shared.b16 {%0,%1,%2,%3}, [%4];"
        : "=r"(r[0]), "=r"(r[1]), "=r"(r[2]), "=r"(r[3]) : "r"(addr));
}

// ======================= small kernels =======================
__global__ void k_emb_l1(const float* __restrict__ attrs,
                         const float* __restrict__ w0,
                         const float* __restrict__ b0) {
    long long idx = (long long)blockIdx.x * blockDim.x + threadIdx.x;
    if (idx >= (long long)NEDGES * DD) return;
    int i = (int)(idx / DD);
    int j = (int)(idx % DD);
    float v = b0[j];
    v += attrs[i * 4 + 0] * w0[0 * DD + j];
    v += attrs[i * 4 + 1] * w0[1 * DD + j];
    v += attrs[i * 4 + 2] * w0[2 * DD + j];
    v += attrs[i * 4 + 3] * w0[3 * DD + j];
    g_h16[idx] = __float2half_rn(silu_f(v));
}

__global__ void k_zero(float* __restrict__ p, long long n) {
    long long i = (long long)blockIdx.x * blockDim.x + threadIdx.x;
    long long stride = (long long)gridDim.x * blockDim.x;
    for (; i < n; i += stride) p[i] = 0.0f;
}

__global__ void k_tohalf(const float* __restrict__ in, __half* __restrict__ out, long long n) {
    long long i = ((long long)blockIdx.x * blockDim.x + threadIdx.x) * 4;
    long long stride = (long long)gridDim.x * blockDim.x * 4;
    for (; i < n; i += stride) {
        float4 v = *(const float4*)(in + i);
        __half2 h0 = __floats2half2_rn(v.x, v.y);
        __half2 h1 = __floats2half2_rn(v.z, v.w);
        *(uint2*)(out + i) = make_uint2(*(uint32_t*)&h0, *(uint32_t*)&h1);
    }
}

// Wh[n][k] = fp16(W[k][n])
__global__ void k_transpose(const float* __restrict__ in, __half* __restrict__ out,
                            int K, int N) {
    __shared__ float t[32][33];
    int k0 = blockIdx.x * 32, n0 = blockIdx.y * 32;
#pragma unroll
    for (int i = 0; i < 4; i++) {
        int k = k0 + threadIdx.y + i * 8;
        int n = n0 + threadIdx.x;
        t[threadIdx.y + i * 8][threadIdx.x] = (k < K && n < N) ? in[(size_t)k * N + n] : 0.f;
    }
    __syncthreads();
#pragma unroll
    for (int i = 0; i < 4; i++) {
        int n = n0 + threadIdx.y + i * 8;
        int k = k0 + threadIdx.x;
        if (n < N && k < K)
            out[(size_t)n * K + k] = __float2half_rn(t[threadIdx.x][threadIdx.y + i * 8]);
    }
}

// ======================= fp16 mma.sync GEMM =======================
// AMODE 0: plain A0 (fp16 if A16 else fp32), K arbitrary.
// AMODE 1: [mesh16[gidx0] | grid16[gidx1] | g_e(fp32)] K=1536.
// AMODE 2: [grid16 | agg(fp32)] K=1024.
// C16: store output as fp16 (pure hidden buffers). Grid: (colTiles, rowTiles).
template <int AMODE, bool A16, bool C16, bool SILU_, bool RESID_, bool SCATTER_, bool STORE_>
__global__ void __launch_bounds__(THREADS)
k_mma(const void* __restrict__ A0, const void* __restrict__ A1,
      const void* __restrict__ A2,
      const int* __restrict__ gidx0, const int* __restrict__ gidx1,
      const __half* __restrict__ Wh, const float* __restrict__ bias,
      const float* __restrict__ resid,
      void* __restrict__ C,
      float* __restrict__ scat, const int* __restrict__ scat_idx,
      int M, int N, int K) {
    extern __shared__ char smraw[];
    __half* sA = (__half*)(smraw + SA_OFF);
    __half* sB = (__half*)(smraw + SB_OFF);
    float* sbias = (float*)(smraw + SBIAS_OFF);
    int* sI0 = (int*)(smraw + SI0_OFF);
    int* sI1 = (int*)(smraw + SI1_OFF);
    int* sIdx = (int*)(smraw + SIDX_OFF);

    const int tid = threadIdx.x;
    const int lane = tid & 31;
    const int wid = tid >> 5;
    const int m0 = blockIdx.y * MT;      // rows on slow dim
    const int n0 = blockIdx.x * NT;      // col tiles on fast dim (L2 A-sharing)

    if (tid < 128) {
        sbias[tid] = (n0 + tid < N) ? bias[n0 + tid] : 0.0f;
        int gr = m0 + tid; if (gr >= M) gr = M - 1;
        if (AMODE == 1) { sI0[tid] = gidx0[gr]; sI1[tid] = gidx1[gr]; }
        if (SCATTER_) sIdx[tid] = scat_idx[gr];
    }
    __syncthreads();

    const int arow = tid >> 3;        // 0..31
    const int aq = tid & 7;           // 0..7 : 4-elem unit
    const int brow = tid >> 2;        // 0..63
    const int bu = tid & 3;           // 0..3

    uint2 rha[4];
    uint4 rbv[2];

    auto loadA = [&](int kc0) {
#pragma unroll
        for (int j = 0; j < 4; j++) {
            int row = arow + j * 32;
            int gr = m0 + row; if (gr >= M) gr = M - 1;
            bool f16; const void* base; size_t off;
            if (AMODE == 0) {
                f16 = A16; base = A0; off = (size_t)gr * K + kc0;
            } else if (AMODE == 1) {
                if (kc0 < DD)          { f16 = true;  base = A0; off = (size_t)sI0[row] * DD + kc0; }
                else if (kc0 < 2 * DD) { f16 = true;  base = A1; off = (size_t)sI1[row] * DD + (kc0 - DD); }
                else                   { f16 = false; base = A2; off = (size_t)gr * DD + (kc0 - 2 * DD); }
            } else {
                if (kc0 < DD) { f16 = true;  base = A0; off = (size_t)gr * DD + kc0; }
                else          { f16 = false; base = A1; off = (size_t)gr * DD + (kc0 - DD); }
            }
            if (f16) {
                rha[j] = *(const uint2*)((const __half*)base + off + aq * 4);
            } else {
                float4 v = *(const float4*)((const float*)base + off + aq * 4);
                __half2 h0 = __floats2half2_rn(v.x, v.y);
                __half2 h1 = __floats2half2_rn(v.z, v.w);
                rha[j] = make_uint2(*(uint32_t*)&h0, *(uint32_t*)&h1);
            }
        }
    };
    auto loadB = [&](int kc0) {
#pragma unroll
        for (int j = 0; j < 2; j++) {
            int row = brow + j * 64;
            int n = n0 + row;
            if (n < N) rbv[j] = *(const uint4*)(Wh + (size_t)n * K + kc0 + bu * 8);
            else       rbv[j] = make_uint4(0, 0, 0, 0);
        }
    };
    auto stsAB = [&](int buf) {
        __half* dA = sA + buf * (128 * HSTRIDE);
        __half* dB = sB + buf * (128 * HSTRIDE);
#pragma unroll
        for (int j = 0; j < 4; j++) {
            int row = arow + j * 32;
            *(uint2*)(dA + row * HSTRIDE + aq * 4) = rha[j];
        }
#pragma unroll
        for (int j = 0; j < 2; j++) {
            int row = brow + j * 64;
            *(uint4*)(dB + row * HSTRIDE + bu * 8) = rbv[j];
        }
    };

    float acc[4][4][4] = {};
    const int wm = wid >> 2;
    const int wn = wid & 3;
    const int r = lane >> 2;
    const int c = lane & 3;

    const uint32_t a_lane_off = (uint32_t)((wm * 64 + (lane & 15)) * HSTRIDE + ((lane >> 4) & 1) * 8);
    const uint32_t b_lane_off = (uint32_t)((wn * 32 + ((lane >> 4) & 1) * 8 + (lane & 7)) * HSTRIDE
                                           + ((lane >> 3) & 1) * 8);
    const uint32_t sA_u32 = (uint32_t)__cvta_generic_to_shared(sA);
    const uint32_t sB_u32 = (uint32_t)__cvta_generic_to_shared(sB);

    const int nch = K / KCH;
    loadA(0); loadB(0);
    stsAB(0);
    __syncthreads();

    for (int ch = 0; ch < nch; ch++) {
        const int buf = ch & 1;
        if (ch + 1 < nch) { loadA((ch + 1) * KCH); loadB((ch + 1) * KCH); }

        const uint32_t aBase = sA_u32 + (buf * (128 * HSTRIDE) + a_lane_off) * 2;
        const uint32_t bBase = sB_u32 + (buf * (128 * HSTRIDE) + b_lane_off) * 2;
#pragma unroll
        for (int kk = 0; kk < 2; kk++) {
            const int kb = kk * 16;
            uint32_t af[4][4], bf[4][2];
#pragma unroll
            for (int mf = 0; mf < 4; mf++)
                ldsm_x4(af[mf], aBase + (mf * 16 * HSTRIDE + kb) * 2);
#pragma unroll
            for (int g = 0; g < 2; g++) {
                uint32_t bq[4];
                ldsm_x4(bq, bBase + (g * 16 * HSTRIDE + kb) * 2);
                bf[2 * g][0] = bq[0]; bf[2 * g][1] = bq[1];
                bf[2 * g + 1][0] = bq[2]; bf[2 * g + 1][1] = bq[3];
            }
#pragma unroll
            for (int mf = 0; mf < 4; mf++)
#pragma unroll
                for (int nf = 0; nf < 4; nf++)
                    mma_f16(acc[mf][nf], af[mf], bf[nf]);
        }
        if (ch + 1 < nch) stsAB((ch + 1) & 1);
        __syncthreads();
    }

    // ---- epilogue ----
#pragma unroll
    for (int mf = 0; mf < 4; mf++) {
        const int lr0 = wm * 64 + mf * 16 + r;
        const int lr1 = lr0 + 8;
        const int row0 = m0 + lr0;
        const int row1 = m0 + lr1;
        int sidx0 = 0, sidx1 = 0;
        if (SCATTER_) { sidx0 = sIdx[lr0]; sidx1 = sIdx[lr1]; }
#pragma unroll
        for (int nf = 0; nf < 4; nf++) {
            const int lc = wn * 32 + nf * 8 + c * 2;
            const int n = n0 + lc;
#pragma unroll
            for (int half_ = 0; half_ < 2; half_++) {
                const int row = half_ ? row1 : row0;
                const int sidx = half_ ? sidx1 : sidx0;
                if (row >= M) continue;
#pragma unroll
                for (int jj = 0; jj < 2; jj++) {
                    const int nn = n + jj;
                    if (nn >= N) continue;
                    float v = acc[mf][nf][half_ * 2 + jj] + sbias[lc + jj];
                    if (SILU_) v = silu_f(v);
                    if (RESID_) v += resid[(size_t)row * DD + nn];
                    if (STORE_) {
                        if (C16) ((__half*)C)[(size_t)row * N + nn] = __float2half_rn(v);
                        else     ((float*)C)[(size_t)row * N + nn] = v;
                    }
                    if (SCATTER_) atomicAdd(&scat[(size_t)sidx * DD + nn], v);
                }
            }
        }
    }
}

// ======================= host =======================
extern "C" void kernel_launch(void* const* d_in, const int* in_sizes, int n_in,
                              void* d_out, int out_size) {
    const float* mesh    = (const float*)d_in[0];
    const float* grid    = (const float*)d_in[1];
    const float* attrs   = (const float*)d_in[2];
    const int*   esrc    = (const int*)d_in[3];
    const int*   edst    = (const int*)d_in[4];
    const float* emb_w0  = (const float*)d_in[5];
    const float* emb_b0  = (const float*)d_in[6];
    const float* emb_w1  = (const float*)d_in[7];
    const float* emb_b1  = (const float*)d_in[8];
    const float* edge_w0 = (const float*)d_in[9];
    const float* edge_b0 = (const float*)d_in[10];
    const float* edge_w1 = (const float*)d_in[11];
    const float* edge_b1 = (const float*)d_in[12];
    const float* node_w0 = (const float*)d_in[13];
    const float* node_b0 = (const float*)d_in[14];
    const float* node_w1 = (const float*)d_in[15];
    const float* node_b1 = (const float*)d_in[16];
    const float* out_w0  = (const float*)d_in[17];
    const float* out_b0  = (const float*)d_in[18];
    const float* out_w1  = (const float*)d_in[19];
    const float* out_b1  = (const float*)d_in[20];
    float* out = (float*)d_out;

    float *ge, *gagg;
    __half *gh16, *gnh16, *gg216, *goh16, *gmesh16, *ggrid16, *gwh;
    cudaGetSymbolAddress((void**)&ge, g_e);
    cudaGetSymbolAddress((void**)&gh16, g_h16);
    cudaGetSymbolAddress((void**)&gagg, g_agg);
    cudaGetSymbolAddress((void**)&gnh16, g_nh16);
    cudaGetSymbolAddress((void**)&gg216, g_g2_16);
    cudaGetSymbolAddress((void**)&goh16, g_oh16);
    cudaGetSymbolAddress((void**)&gmesh16, g_mesh16);
    cudaGetSymbolAddress((void**)&ggrid16, g_grid16);
    cudaGetSymbolAddress((void**)&gwh, g_wh);

    // unique instantiations
    cudaFuncSetAttribute(k_mma<0, true,  false, false, false, false, true>,  cudaFuncAttributeMaxDynamicSharedMemorySize, SMEM_BYTES);
    cudaFuncSetAttribute(k_mma<1, false, true,  true,  false, false, true>,  cudaFuncAttributeMaxDynamicSharedMemorySize, SMEM_BYTES);
    cudaFuncSetAttribute(k_mma<0, true,  false, false, true,  true,  false>, cudaFuncAttributeMaxDynamicSharedMemorySize, SMEM_BYTES);
    cudaFuncSetAttribute(k_mma<2, false, true,  true,  false, false, true>,  cudaFuncAttributeMaxDynamicSharedMemorySize, SMEM_BYTES);
    cudaFuncSetAttribute(k_mma<0, true,  true,  false, true,  false, true>,  cudaFuncAttributeMaxDynamicSharedMemorySize, SMEM_BYTES);
    cudaFuncSetAttribute(k_mma<0, true,  true,  true,  false, false, true>,  cudaFuncAttributeMaxDynamicSharedMemorySize, SMEM_BYTES);

    // ---- weight transpose + fp16 input copies ----
    dim3 tb(32, 8);
    k_transpose<<<dim3(16, 16), tb>>>(emb_w1,  gwh + WT_EMB1,  DD, DD);
    k_transpose<<<dim3(48, 16), tb>>>(edge_w0, gwh + WT_EDGE0, 3 * DD, DD);
    k_transpose<<<dim3(16, 16), tb>>>(edge_w1, gwh + WT_EDGE1, DD, DD);
    k_transpose<<<dim3(32, 16), tb>>>(node_w0, gwh + WT_NODE0, 2 * DD, DD);
    k_transpose<<<dim3(16, 16), tb>>>(node_w1, gwh + WT_NODE1, DD, DD);
    k_transpose<<<dim3(16, 16), tb>>>(out_w0,  gwh + WT_OUT0,  DD, DD);
    k_transpose<<<dim3(16, 15), tb>>>(out_w1,  gwh + WT_OUT1,  DD, OUTD);
    k_tohalf<<<2048, 256>>>(mesh, gmesh16, (long long)NMESH * DD);
    k_tohalf<<<2048, 256>>>(grid, ggrid16, (long long)NGRID * DD);

    const int TE = (NEDGES + MT - 1) / MT;  // 1528
    const int TG = (NGRID + MT - 1) / MT;   // 510
    const int CN = (DD + NT - 1) / NT;      // 4
    const int CO = (OUTD + NT - 1) / NT;    // 4

    // 1) emb L1 (fp32 math, fp16 store)
    {
        long long n = (long long)NEDGES * DD;
        k_emb_l1<<<(unsigned)((n + 255) / 256), 256>>>(attrs, emb_w0, emb_b0);
    }
    // 2) emb L2: g_e = g_h16 @ emb_w1 + b1   (fp32 out, residual source)
    k_mma<0, true, false, false, false, false, true><<<dim3(CN, TE), THREADS, SMEM_BYTES>>>(
        gh16, nullptr, nullptr, nullptr, nullptr, gwh + WT_EMB1, emb_b1,
        nullptr, ge, nullptr, nullptr, NEDGES, DD, DD);
    // 3) zero agg
    k_zero<<<2048, 256>>>(gagg, (long long)NGRID * DD);
    // 4) edge L1 (gather-concat): g_h16 = silu([mesh16[src]|grid16[dst]|g_e] @ edge_w0 + b0)
    k_mma<1, false, true, true, false, false, true><<<dim3(CN, TE), THREADS, SMEM_BYTES>>>(
        gmesh16, ggrid16, ge, esrc, edst, gwh + WT_EDGE0, edge_b0,
        nullptr, gh16, nullptr, nullptr, NEDGES, DD, 3 * DD);
    // 5) edge L2 + residual + scatter: agg[dst] += g_e + g_h16 @ edge_w1 + b1
    k_mma<0, true, false, false, true, true, false><<<dim3(CN, TE), THREADS, SMEM_BYTES>>>(
        gh16, nullptr, nullptr, nullptr, nullptr, gwh + WT_EDGE1, edge_b1,
        ge, nullptr, gagg, edst, NEDGES, DD, DD);
    // 6) node L1: g_nh16 = silu([grid16|agg] @ node_w0 + b0)
    k_mma<2, false, true, true, false, false, true><<<dim3(CN, TG), THREADS, SMEM_BYTES>>>(
        ggrid16, gagg, nullptr, nullptr, nullptr, gwh + WT_NODE0, node_b0,
        nullptr, gnh16, nullptr, nullptr, NGRID, DD, 2 * DD);
    // 7) node L2 + residual(fp32 grid): g_g2_16 = grid + g_nh16 @ node_w1 + b1
    k_mma<0, true, true, false, true, false, true><<<dim3(CN, TG), THREADS, SMEM_BYTES>>>(
        gnh16, nullptr, nullptr, nullptr, nullptr, gwh + WT_NODE1, node_b1,
        grid, gg216, nullptr, nullptr, NGRID, DD, DD);
    // 8) out L1: g_oh16 = silu(g_g2_16 @ out_w0 + b0)
    k_mma<0, true, true, true, false, false, true><<<dim3(CN, TG), THREADS, SMEM_BYTES>>>(
        gg216, nullptr, nullptr, nullptr, nullptr, gwh + WT_OUT0, out_b0,
        nullptr, goh16, nullptr, nullptr, NGRID, DD, DD);
    // 9) out L2: out = g_oh16 @ out_w1 + b1 (fp32, N=471)
    k_mma<0, true, false, false, false, false, true><<<dim3(CO, TG), THREADS, SMEM_BYTES>>>(
        goh16, nullptr, nullptr, nullptr, nullptr, gwh + WT_OUT1, out_b1,
        nullptr, out, nullptr, nullptr, NGRID, OUTD, DD);
}

// round 13
// speedup vs baseline: 7.0436x; 1.0973x over previous
#include <cuda_runtime.h>
#include <cuda_fp16.h>
#include <cstdint>

#define NMESH 10242
#define NGRID 65160
#define NEDGES 195480
#define DD 512
#define OUTD 471

#define THREADS 256
#define MT 128
#define NT 128
#define KCH 32
#define HSTRIDE 40      // smem row stride in fp16 units

// ---- smem layout (bytes) ----
#define SA_OFF 0
#define SB_OFF 20480
#define SBIAS_OFF 40960
#define SI0_OFF 41472
#define SI1_OFF 41984
#define SIDX_OFF 42496
#define SMEM_BYTES 43008

// ---- scratch ----
__device__ float  g_e[(size_t)NEDGES * DD];       // fp32 (residual source)
__device__ __half g_h16[(size_t)NEDGES * DD];
__device__ float  g_agg[(size_t)NGRID * DD];      // fp32 (atomic accumulate)
__device__ __half g_nh16[(size_t)NGRID * DD];
__device__ __half g_g2_16[(size_t)NGRID * DD];
__device__ __half g_oh16[(size_t)NGRID * DD];
__device__ __half g_mesh16[(size_t)NMESH * DD];
__device__ __half g_grid16[(size_t)NGRID * DD];
__device__ __half g_wh[2600448];

#define WT_EMB1   0
#define WT_EDGE0  262144
#define WT_EDGE1  1048576
#define WT_NODE0  1310720
#define WT_NODE1  1835008
#define WT_OUT0   2097152
#define WT_OUT1   2359296

__device__ __forceinline__ float silu_f(float v) { return v / (1.0f + __expf(-v)); }

__device__ __forceinline__ void mma_f16(float (&d)[4], const uint32_t (&a)[4],
                                        const uint32_t (&b)[2]) {
    asm volatile(
        "mma.sync.aligned.m16n8k16.row.col.f32.f16.f16.f32 "
        "{%0,%1,%2,%3}, {%4,%5,%6,%7}, {%8,%9}, {%0,%1,%2,%3};"
        : "+f"(d[0]), "+f"(d[1]), "+f"(d[2]), "+f"(d[3])
        : "r"(a[0]), "r"(a[1]), "r"(a[2]), "r"(a[3]), "r"(b[0]), "r"(b[1]));
}

__device__ __forceinline__ void ldsm_x4(uint32_t (&r)[4], uint32_t addr) {
    asm volatile("ldmatrix.sync.aligned.m8n8.x4.shared.b16 {%0,%1,%2,%3}, [%4];"
        : "=r"(r[0]), "=r"(r[1]), "=r"(r[2]), "=r"(r[3]) : "r"(addr));
}

__device__ __forceinline__ void cp8(uint32_t dst, const void* src) {
    asm volatile("cp.async.ca.shared.global [%0], [%1], 8;" :: "r"(dst), "l"(src) : "memory");
}
__device__ __forceinline__ void cp16z(uint32_t dst, const void* src, int sz) {
    asm volatile("cp.async.cg.shared.global [%0], [%1], 16, %2;"
                 :: "r"(dst), "l"(src), "r"(sz) : "memory");
}
#define CP_COMMIT() asm volatile("cp.async.commit_group;" ::: "memory")
#define CP_WAIT0()  asm volatile("cp.async.wait_group 0;" ::: "memory")

// ======================= prologue kernels (merged) =======================
// All 7 weight transposes in ONE launch. Wh[n][k] = fp16(W[k][n]).
__global__ void k_prep_w(const float* __restrict__ emb_w1, const float* __restrict__ edge_w0,
                         const float* __restrict__ edge_w1, const float* __restrict__ node_w0,
                         const float* __restrict__ node_w1, const float* __restrict__ out_w0,
                         const float* __restrict__ out_w1, __half* __restrict__ gwh) {
    int t = blockIdx.x;
    const float* in; __half* out; int K, N, tk;
    if (t < 256)       { in = emb_w1;  out = gwh + WT_EMB1;  K = 512;  N = 512; t -= 0;    tk = 16; }
    else if (t < 1024) { in = edge_w0; out = gwh + WT_EDGE0; K = 1536; N = 512; t -= 256;  tk = 48; }
    else if (t < 1280) { in = edge_w1; out = gwh + WT_EDGE1; K = 512;  N = 512; t -= 1024; tk = 16; }
    else if (t < 1792) { in = node_w0; out = gwh + WT_NODE0; K = 1024; N = 512; t -= 1280; tk = 32; }
    else if (t < 2048) { in = node_w1; out = gwh + WT_NODE1; K = 512;  N = 512; t -= 1792; tk = 16; }
    else if (t < 2304) { in = out_w0;  out = gwh + WT_OUT0;  K = 512;  N = 512; t -= 2048; tk = 16; }
    else               { in = out_w1;  out = gwh + WT_OUT1;  K = 512;  N = 471; t -= 2304; tk = 16; }
    int k0 = (t % tk) * 32, n0 = (t / tk) * 32;
    __shared__ float tt[32][33];
#pragma unroll
    for (int i = 0; i < 4; i++) {
        int k = k0 + threadIdx.y + i * 8;
        int n = n0 + threadIdx.x;
        tt[threadIdx.y + i * 8][threadIdx.x] = (k < K && n < N) ? in[(size_t)k * N + n] : 0.f;
    }
    __syncthreads();
#pragma unroll
    for (int i = 0; i < 4; i++) {
        int n = n0 + threadIdx.y + i * 8;
        int k = k0 + threadIdx.x;
        if (n < N && k < K)
            out[(size_t)n * K + k] = __float2half_rn(tt[threadIdx.x][threadIdx.y + i * 8]);
    }
}

// mesh+grid fp16 casts in ONE launch.
__global__ void k_prep_act(const float* __restrict__ mesh, const float* __restrict__ grid,
                           __half* __restrict__ m16, __half* __restrict__ g16) {
    const long long nm = (long long)NMESH * DD;       // multiple of 4
    const long long total = nm + (long long)NGRID * DD;
    long long i = ((long long)blockIdx.x * blockDim.x + threadIdx.x) * 4;
    long long stride = (long long)gridDim.x * blockDim.x * 4;
    for (; i < total; i += stride) {
        const float* src; __half* dst; long long off;
        if (i < nm) { src = mesh; dst = m16; off = i; }
        else        { src = grid; dst = g16; off = i - nm; }
        float4 v = *(const float4*)(src + off);
        __half2 h0 = __floats2half2_rn(v.x, v.y);
        __half2 h1 = __floats2half2_rn(v.z, v.w);
        *(uint2*)(dst + off) = make_uint2(*(uint32_t*)&h0, *(uint32_t*)&h1);
    }
}

__global__ void k_emb_l1(const float* __restrict__ attrs,
                         const float* __restrict__ w0,
                         const float* __restrict__ b0) {
    long long idx = (long long)blockIdx.x * blockDim.x + threadIdx.x;
    if (idx >= (long long)NEDGES * DD) return;
    int i = (int)(idx / DD);
    int j = (int)(idx % DD);
    float v = b0[j];
    v += attrs[i * 4 + 0] * w0[0 * DD + j];
    v += attrs[i * 4 + 1] * w0[1 * DD + j];
    v += attrs[i * 4 + 2] * w0[2 * DD + j];
    v += attrs[i * 4 + 3] * w0[3 * DD + j];
    g_h16[idx] = __float2half_rn(silu_f(v));
}

__global__ void k_zero(float* __restrict__ p, long long n) {
    long long i = (long long)blockIdx.x * blockDim.x + threadIdx.x;
    long long stride = (long long)gridDim.x * blockDim.x;
    for (; i < n; i += stride) p[i] = 0.0f;
}

// ======================= fp16 mma.sync GEMM (cp.async pipeline) =======================
// AMODE 0: plain A0 (A16 flag). 1: [mesh16[g0]|grid16[g1]|g_e(f32)] K=1536.
// 2: [grid16|agg(f32)] K=1024. Grid: (colTiles, rowTiles).
template <int AMODE, bool A16, bool C16, bool SILU_, bool RESID_, bool SCATTER_, bool STORE_>
__global__ void __launch_bounds__(THREADS)
k_mma(const void* __restrict__ A0, const void* __restrict__ A1,
      const void* __restrict__ A2,
      const int* __restrict__ gidx0, const int* __restrict__ gidx1,
      const __half* __restrict__ Wh, const float* __restrict__ bias,
      const float* __restrict__ resid,
      void* __restrict__ C,
      float* __restrict__ scat, const int* __restrict__ scat_idx,
      int M, int N, int K) {
    extern __shared__ char smraw[];
    __half* sA = (__half*)(smraw + SA_OFF);
    __half* sB = (__half*)(smraw + SB_OFF);
    float* sbias = (float*)(smraw + SBIAS_OFF);
    int* sI0 = (int*)(smraw + SI0_OFF);
    int* sI1 = (int*)(smraw + SI1_OFF);
    int* sIdx = (int*)(smraw + SIDX_OFF);

    const int tid = threadIdx.x;
    const int lane = tid & 31;
    const int wid = tid >> 5;
    const int m0 = blockIdx.y * MT;
    const int n0 = blockIdx.x * NT;

    if (tid < 128) {
        sbias[tid] = (n0 + tid < N) ? bias[n0 + tid] : 0.0f;
        int gr = m0 + tid; if (gr >= M) gr = M - 1;
        if (AMODE == 1) { sI0[tid] = gidx0[gr]; sI1[tid] = gidx1[gr]; }
        if (SCATTER_) sIdx[tid] = scat_idx[gr];
    }
    __syncthreads();

    const int arow = tid >> 3;        // 0..31
    const int aq = tid & 7;           // 0..7
    const int brow = tid >> 2;        // 0..63
    const int bu = tid & 3;           // 0..3

    const uint32_t sA_u32 = (uint32_t)__cvta_generic_to_shared(sA);
    const uint32_t sB_u32 = (uint32_t)__cvta_generic_to_shared(sB);

    float4 ra[4];   // staging for fp32 segments only

    // issue loads for chunk chn: cp.async for fp16 parts, LDG->reg for fp32 parts.
    auto issueAB = [&](int chn) -> bool {
        const int kc0 = chn * KCH;
        const int buf = chn & 1;
        const uint32_t dAbase = sA_u32 + buf * (128 * HSTRIDE) * 2;
        const uint32_t dBbase = sB_u32 + buf * (128 * HSTRIDE) * 2;
        bool f32seg;
        if (AMODE == 1)      f32seg = (kc0 >= 2 * DD);
        else if (AMODE == 2) f32seg = (kc0 >= DD);
        else                 f32seg = !A16;
        if (!f32seg) {
#pragma unroll
            for (int j = 0; j < 4; j++) {
                int row = arow + j * 32;
                int gr = m0 + row; if (gr >= M) gr = M - 1;
                const __half* src;
                if (AMODE == 0) {
                    src = (const __half*)A0 + (size_t)gr * K + kc0;
                } else if (AMODE == 1) {
                    src = (kc0 < DD) ? (const __half*)A0 + (size_t)sI0[row] * DD + kc0
                                     : (const __half*)A1 + (size_t)sI1[row] * DD + (kc0 - DD);
                } else {
                    src = (const __half*)A0 + (size_t)gr * DD + kc0;
                }
                cp8(dAbase + (row * HSTRIDE + aq * 4) * 2, src + aq * 4);
            }
        } else {
#pragma unroll
            for (int j = 0; j < 4; j++) {
                int row = arow + j * 32;
                int gr = m0 + row; if (gr >= M) gr = M - 1;
                const float* src;
                if (AMODE == 1)      src = (const float*)A2 + (size_t)gr * DD + (kc0 - 2 * DD);
                else if (AMODE == 2) src = (const float*)A1 + (size_t)gr * DD + (kc0 - DD);
                else                 src = (const float*)A0 + (size_t)gr * K + kc0;
                ra[j] = *(const float4*)(src + aq * 4);
            }
        }
#pragma unroll
        for (int j = 0; j < 2; j++) {
            int row = brow + j * 64;
            int n = n0 + row;
            int nn = (n < N) ? n : (N - 1);
            const __half* src = Wh + (size_t)nn * K + kc0 + bu * 8;
            cp16z(dBbase + (row * HSTRIDE + bu * 8) * 2, src, (n < N) ? 16 : 0);
        }
        CP_COMMIT();
        return f32seg;
    };
    auto stsA32 = [&](int chn) {
        const int buf = chn & 1;
        __half* dA = sA + buf * (128 * HSTRIDE);
#pragma unroll
        for (int j = 0; j < 4; j++) {
            int row = arow + j * 32;
            float4 v = ra[j];
            __half2 h0 = __floats2half2_rn(v.x, v.y);
            __half2 h1 = __floats2half2_rn(v.z, v.w);
            *(uint2*)(dA + row * HSTRIDE + aq * 4) = make_uint2(*(uint32_t*)&h0, *(uint32_t*)&h1);
        }
    };

    float acc[4][4][4] = {};
    const int wm = wid >> 2;
    const int wn = wid & 3;
    const int r = lane >> 2;
    const int c = lane & 3;

    const uint32_t a_lane_off = (uint32_t)((wm * 64 + (lane & 15)) * HSTRIDE + ((lane >> 4) & 1) * 8);
    const uint32_t b_lane_off = (uint32_t)((wn * 32 + ((lane >> 4) & 1) * 8 + (lane & 7)) * HSTRIDE
                                           + ((lane >> 3) & 1) * 8);

    const int nch = K / KCH;
    {
        bool f32p = issueAB(0);
        if (f32p) stsA32(0);
        CP_WAIT0();
        __syncthreads();
    }

    for (int ch = 0; ch < nch; ch++) {
        const int buf = ch & 1;
        bool f32n = false;
        if (ch + 1 < nch) f32n = issueAB(ch + 1);

        const uint32_t aBase = sA_u32 + (buf * (128 * HSTRIDE) + a_lane_off) * 2;
        const uint32_t bBase = sB_u32 + (buf * (128 * HSTRIDE) + b_lane_off) * 2;
#pragma unroll
        for (int kk = 0; kk < 2; kk++) {
            const int kb = kk * 16;
            uint32_t af[4][4], bf[4][2];
#pragma unroll
            for (int mf = 0; mf < 4; mf++)
                ldsm_x4(af[mf], aBase + (mf * 16 * HSTRIDE + kb) * 2);
#pragma unroll
            for (int g = 0; g < 2; g++) {
                uint32_t bq[4];
                ldsm_x4(bq, bBase + (g * 16 * HSTRIDE + kb) * 2);
                bf[2 * g][0] = bq[0]; bf[2 * g][1] = bq[1];
                bf[2 * g + 1][0] = bq[2]; bf[2 * g + 1][1] = bq[3];
            }
#pragma unroll
            for (int mf = 0; mf < 4; mf++)
#pragma unroll
                for (int nf = 0; nf < 4; nf++)
                    mma_f16(acc[mf][nf], af[mf], bf[nf]);
        }
        if (f32n) stsA32(ch + 1);
        CP_WAIT0();
        __syncthreads();
    }

    // ---- epilogue ----
#pragma unroll
    for (int mf = 0; mf < 4; mf++) {
        const int lr0 = wm * 64 + mf * 16 + r;
        const int lr1 = lr0 + 8;
        const int row0 = m0 + lr0;
        const int row1 = m0 + lr1;
        int sidx0 = 0, sidx1 = 0;
        if (SCATTER_) { sidx0 = sIdx[lr0]; sidx1 = sIdx[lr1]; }
#pragma unroll
        for (int nf = 0; nf < 4; nf++) {
            const int lc = wn * 32 + nf * 8 + c * 2;
            const int n = n0 + lc;
#pragma unroll
            for (int half_ = 0; half_ < 2; half_++) {
                const int row = half_ ? row1 : row0;
                const int sidx = half_ ? sidx1 : sidx0;
                if (row >= M) continue;
#pragma unroll
                for (int jj = 0; jj < 2; jj++) {
                    const int nn = n + jj;
                    if (nn >= N) continue;
                    float v = acc[mf][nf][half_ * 2 + jj] + sbias[lc + jj];
                    if (SILU_) v = silu_f(v);
                    if (RESID_) v += resid[(size_t)row * DD + nn];
                    if (STORE_) {
                        if (C16) ((__half*)C)[(size_t)row * N + nn] = __float2half_rn(v);
                        else     ((float*)C)[(size_t)row * N + nn] = v;
                    }
                    if (SCATTER_) atomicAdd(&scat[(size_t)sidx * DD + nn], v);
                }
            }
        }
    }
}

// ======================= host =======================
extern "C" void kernel_launch(void* const* d_in, const int* in_sizes, int n_in,
                              void* d_out, int out_size) {
    const float* mesh    = (const float*)d_in[0];
    const float* grid    = (const float*)d_in[1];
    const float* attrs   = (const float*)d_in[2];
    const int*   esrc    = (const int*)d_in[3];
    const int*   edst    = (const int*)d_in[4];
    const float* emb_w0  = (const float*)d_in[5];
    const float* emb_b0  = (const float*)d_in[6];
    const float* emb_w1  = (const float*)d_in[7];
    const float* emb_b1  = (const float*)d_in[8];
    const float* edge_w0 = (const float*)d_in[9];
    const float* edge_b0 = (const float*)d_in[10];
    const float* edge_w1 = (const float*)d_in[11];
    const float* edge_b1 = (const float*)d_in[12];
    const float* node_w0 = (const float*)d_in[13];
    const float* node_b0 = (const float*)d_in[14];
    const float* node_w1 = (const float*)d_in[15];
    const float* node_b1 = (const float*)d_in[16];
    const float* out_w0  = (const float*)d_in[17];
    const float* out_b0  = (const float*)d_in[18];
    const float* out_w1  = (const float*)d_in[19];
    const float* out_b1  = (const float*)d_in[20];
    float* out = (float*)d_out;

    float *ge, *gagg;
    __half *gh16, *gnh16, *gg216, *goh16, *gmesh16, *ggrid16, *gwh;
    cudaGetSymbolAddress((void**)&ge, g_e);
    cudaGetSymbolAddress((void**)&gh16, g_h16);
    cudaGetSymbolAddress((void**)&gagg, g_agg);
    cudaGetSymbolAddress((void**)&gnh16, g_nh16);
    cudaGetSymbolAddress((void**)&gg216, g_g2_16);
    cudaGetSymbolAddress((void**)&goh16, g_oh16);
    cudaGetSymbolAddress((void**)&gmesh16, g_mesh16);
    cudaGetSymbolAddress((void**)&ggrid16, g_grid16);
    cudaGetSymbolAddress((void**)&gwh, g_wh);

    cudaFuncSetAttribute(k_mma<0, true,  false, false, false, false, true>,  cudaFuncAttributeMaxDynamicSharedMemorySize, SMEM_BYTES);
    cudaFuncSetAttribute(k_mma<1, false, true,  true,  false, false, true>,  cudaFuncAttributeMaxDynamicSharedMemorySize, SMEM_BYTES);
    cudaFuncSetAttribute(k_mma<0, true,  false, false, true,  true,  false>, cudaFuncAttributeMaxDynamicSharedMemorySize, SMEM_BYTES);
    cudaFuncSetAttribute(k_mma<2, false, true,  true,  false, false, true>,  cudaFuncAttributeMaxDynamicSharedMemorySize, SMEM_BYTES);
    cudaFuncSetAttribute(k_mma<0, true,  true,  false, true,  false, true>,  cudaFuncAttributeMaxDynamicSharedMemorySize, SMEM_BYTES);
    cudaFuncSetAttribute(k_mma<0, true,  true,  true,  false, false, true>,  cudaFuncAttributeMaxDynamicSharedMemorySize, SMEM_BYTES);

    const int TE = (NEDGES + MT - 1) / MT;  // 1528
    const int TG = (NGRID + MT - 1) / MT;   // 510
    const int CN = (DD + NT - 1) / NT;      // 4
    const int CO = (OUTD + NT - 1) / NT;    // 4

    // launch 0: all weight transposes (one kernel)
    k_prep_w<<<2544, dim3(32, 8)>>>(emb_w1, edge_w0, edge_w1, node_w0, node_w1,
                                    out_w0, out_w1, gwh);
    // launch 1: mesh+grid fp16 casts
    k_prep_act<<<2048, 256>>>(mesh, grid, gmesh16, ggrid16);
    // launch 2: emb L1
    {
        long long n = (long long)NEDGES * DD;
        k_emb_l1<<<(unsigned)((n + 255) / 256), 256>>>(attrs, emb_w0, emb_b0);
    }
    // launch 3: emb L2 -> g_e (fp32)
    k_mma<0, true, false, false, false, false, true><<<dim3(CN, TE), THREADS, SMEM_BYTES>>>(
        gh16, nullptr, nullptr, nullptr, nullptr, gwh + WT_EMB1, emb_b1,
        nullptr, ge, nullptr, nullptr, NEDGES, DD, DD);
    // launch 4: zero agg
    k_zero<<<2048, 256>>>(gagg, (long long)NGRID * DD);
    // launch 5 (ncu -s 5 profiles THIS): edge L1 gather-concat GEMM
    k_mma<1, false, true, true, false, false, true><<<dim3(CN, TE), THREADS, SMEM_BYTES>>>(
        gmesh16, ggrid16, ge, esrc, edst, gwh + WT_EDGE0, edge_b0,
        nullptr, gh16, nullptr, nullptr, NEDGES, DD, 3 * DD);
    // edge L2 + residual + scatter
    k_mma<0, true, false, false, true, true, false><<<dim3(CN, TE), THREADS, SMEM_BYTES>>>(
        gh16, nullptr, nullptr, nullptr, nullptr, gwh + WT_EDGE1, edge_b1,
        ge, nullptr, gagg, edst, NEDGES, DD, DD);
    // node L1
    k_mma<2, false, true, true, false, false, true><<<dim3(CN, TG), THREADS, SMEM_BYTES>>>(
        ggrid16, gagg, nullptr, nullptr, nullptr, gwh + WT_NODE0, node_b0,
        nullptr, gnh16, nullptr, nullptr, NGRID, DD, 2 * DD);
    // node L2 + residual
    k_mma<0, true, true, false, true, false, true><<<dim3(CN, TG), THREADS, SMEM_BYTES>>>(
        gnh16, nullptr, nullptr, nullptr, nullptr, gwh + WT_NODE1, node_b1,
        grid, gg216, nullptr, nullptr, NGRID, DD, DD);
    // out L1
    k_mma<0, true, true, true, false, false, true><<<dim3(CN, TG), THREADS, SMEM_BYTES>>>(
        gg216, nullptr, nullptr, nullptr, nullptr, gwh + WT_OUT0, out_b0,
        nullptr, goh16, nullptr, nullptr, NGRID, DD, DD);
    // out L2 (N=471)
    k_mma<0, true, false, false, false, false, true><<<dim3(CO, TG), THREADS, SMEM_BYTES>>>(
        goh16, nullptr, nullptr, nullptr, nullptr, gwh + WT_OUT1, out_b1,
        nullptr, out, nullptr, nullptr, NGRID, OUTD, DD);
}